// round 13
// baseline (speedup 1.0000x reference)
#include <cuda_runtime.h>
#include <cuda_fp16.h>
#include <stdint.h>

#define BSZ 32
#define NSEQ 20
#define DIM 512
#define HID 512
#define G4 2048          // 4*HID
#define NOUT 7680        // NT*SEM
#define SEM 256
#define NPAIR 190
#define MROWS (BSZ*NPAIR)   // 6080
#define SB (NSEQ*BSZ*HID)   // 640*512 per plane
#define FSZ (BSZ*NSEQ*NSEQ*HID)
#define LSTM_BLOCKS 88

// ---------------- device scratch ----------------
__device__ __half g_WV16[BSZ*NSEQ*DIM];        // masked word vectors fp16
__device__ float g_X[2][BSZ*NSEQ*G4];          // input projections (f, b)
__device__ __half g_H16[2][2][SB];             // [dir][parity] hidden (fp16)
__device__ float g_C[2][SB];                   // cell state
__device__ __half g_WI16[2][G4*DIM];           // W_ih fp16 (f, b)
__device__ __half g_W16[2][G4*HID];            // W_hh fp16 (f, b)
__device__ float g_Ff[FSZ];                    // fp32 cumulative sums
__device__ float g_Fb[FSZ];
__device__ __half g_FF16[FSZ];                 // fp16 cumsum planes (out GEMM)
__device__ __half g_FB16[FSZ];
__device__ __half g_WO16[NOUT*2*HID];          // fp16 w_out
__device__ int   g_psF[NPAIR];
__device__ int   g_psB[NPAIR];
__device__ int   g_pcnt[NPAIR];
__device__ unsigned g_bar;

__device__ __forceinline__ float sigm(float x){ return 1.f/(1.f+__expf(-x)); }

__device__ __forceinline__ void mma16h(float c[4], const uint32_t a[4], const uint32_t b[2]){
  asm volatile("mma.sync.aligned.m16n8k16.row.col.f32.f16.f16.f32 "
      "{%0,%1,%2,%3}, {%4,%5,%6,%7}, {%8,%9}, {%0,%1,%2,%3};\n"
      : "+f"(c[0]), "+f"(c[1]), "+f"(c[2]), "+f"(c[3])
      : "r"(a[0]), "r"(a[1]), "r"(a[2]), "r"(a[3]), "r"(b[0]), "r"(b[1]));
}
__device__ __forceinline__ void ldsm4(uint32_t r[4], uint32_t saddr){
  asm volatile("ldmatrix.sync.aligned.m8n8.x4.shared.b16 {%0,%1,%2,%3}, [%4];"
      : "=r"(r[0]), "=r"(r[1]), "=r"(r[2]), "=r"(r[3]) : "r"(saddr));
}

// ---------------- small setup kernels ----------------
__global__ void zero_state_kernel(){
  int i = blockIdx.x*blockDim.x + threadIdx.x;
  if (i < 4*SB) (&g_H16[0][0][0])[i] = __float2half(0.f);
  if (i < 2*SB) (&g_C[0][0])[i] = 0.f;
}

__global__ void wconv_kernel(const float* __restrict__ wih_f, const float* __restrict__ wih_b,
                             const float* __restrict__ whh_f, const float* __restrict__ whh_b){
  int i = blockIdx.x*blockDim.x + threadIdx.x;
  if (i >= G4*HID) return;
  g_WI16[0][i] = __float2half(wih_f[i]);
  g_WI16[1][i] = __float2half(wih_b[i]);
  g_W16[0][i]  = __float2half(whh_f[i]);
  g_W16[1][i]  = __float2half(whh_b[i]);
}

__global__ void wout16_kernel(const float* __restrict__ w){
  int i = blockIdx.x*blockDim.x + threadIdx.x;
  if (i < NOUT*2*HID) g_WO16[i] = __float2half(w[i]);
}

__global__ void setup_pairs_kernel(){
  if (threadIdx.x == 0) g_bar = 0;           // reset grid barrier each replay
  int p = threadIdx.x;
  if (p >= NPAIR) return;
  int cum = 0, k = 1, s = 0;
  for (int kk = 1; kk < NSEQ; kk++){
    int c = NSEQ - kk;
    if (p < cum + c){ k = kk; s = p - cum; break; }
    cum += c;
  }
  int e = s + k;
  g_psF[p] = s*NSEQ + e;
  g_psB[p] = e*NSEQ + s;
  g_pcnt[p] = k + 1;
}

__global__ void embed_kernel(const int* __restrict__ cap, const int* __restrict__ len,
                             const float* __restrict__ emb){
  int bt = blockIdx.x; int b = bt/NSEQ, t = bt%NSEQ;
  int tok = cap[bt];
  float m = (t < len[b]) ? 1.f : 0.f;
  const float* src = emb + (size_t)tok*DIM;
  for (int n = threadIdx.x; n < DIM; n += blockDim.x)
    g_WV16[bt*DIM + n] = __float2half(m * src[n]);
}

// =======================================================================
// FP16 projection GEMM: X[dir] = WV16 @ WI16[dir]^T + (b_ih + b_hh)
// M=640, N=2048, K=512. BM=BN=128, BK=32, 256 thr. grid (16, 5, 2)
// =======================================================================
__global__ __launch_bounds__(256) void gemm16_bias(
    const float* __restrict__ bif, const float* __restrict__ bhf,
    const float* __restrict__ bib, const float* __restrict__ bhb)
{
  const int dir = blockIdx.z;
  const __half* __restrict__ A = g_WV16;
  const __half* __restrict__ B = g_WI16[dir];
  const float* __restrict__ b1 = dir ? bib : bif;
  const float* __restrict__ b2 = dir ? bhb : bhf;
  float* __restrict__ C = g_X[dir];

  __shared__ __align__(16) __half sA[128][40];
  __shared__ __align__(16) __half sB[128][40];
  const int tid = threadIdx.x, lane = tid & 31, wid = tid >> 5;
  const int warpM = wid >> 2, warpN = wid & 3;
  const int g = lane >> 2, t4 = lane & 3;
  const int bm = blockIdx.y*128, bn = blockIdx.x*128;

  const uint32_t sAu = (uint32_t)__cvta_generic_to_shared(&sA[0][0]);
  const uint32_t sBu = (uint32_t)__cvta_generic_to_shared(&sB[0][0]);
  const int bmat = lane >> 3;
  const uint32_t aOff = ((uint32_t)(warpM*64 + (lane & 15))*40 + (uint32_t)(lane >> 4)*8)*2;
  const uint32_t bOff = ((uint32_t)(warpN*32 + ((bmat >> 1)*8) + (lane & 7))*40
                        + (uint32_t)(bmat & 1)*8)*2;

  const int arow = tid >> 1, ak = (tid & 1)*16;
  uint4 ra[2], rb[2];
  {
    const __half* srcA = A + (size_t)(bm + arow)*DIM + ak;
    ra[0] = *(const uint4*)srcA;
    ra[1] = *(const uint4*)(srcA + 8);
    const __half* srcB = B + (size_t)(bn + arow)*DIM + ak;
    rb[0] = *(const uint4*)srcB;
    rb[1] = *(const uint4*)(srcB + 8);
  }

  float acc[4][4][4] = {};
  for (int k0 = 0; k0 < DIM; k0 += 32){
    __syncthreads();
    *(uint4*)&sA[arow][ak]     = ra[0];
    *(uint4*)&sA[arow][ak + 8] = ra[1];
    *(uint4*)&sB[arow][ak]     = rb[0];
    *(uint4*)&sB[arow][ak + 8] = rb[1];
    __syncthreads();
    if (k0 + 32 < DIM){
      const __half* srcA = A + (size_t)(bm + arow)*DIM + k0 + 32 + ak;
      ra[0] = *(const uint4*)srcA;
      ra[1] = *(const uint4*)(srcA + 8);
      const __half* srcB = B + (size_t)(bn + arow)*DIM + k0 + 32 + ak;
      rb[0] = *(const uint4*)srcB;
      rb[1] = *(const uint4*)(srcB + 8);
    }
    #pragma unroll
    for (int ks = 0; ks < 32; ks += 16){
      uint32_t a[4][4], bq[2][4];
      #pragma unroll
      for (int mt = 0; mt < 4; mt++)
        ldsm4(a[mt], sAu + aOff + (uint32_t)mt*16*80 + (uint32_t)ks*2);
      ldsm4(bq[0], sBu + bOff + (uint32_t)ks*2);
      ldsm4(bq[1], sBu + bOff + 16*80 + (uint32_t)ks*2);
      #pragma unroll
      for (int mt = 0; mt < 4; mt++)
        #pragma unroll
        for (int nt = 0; nt < 4; nt++)
          mma16h(acc[mt][nt], a[mt], &bq[nt>>1][(nt&1)*2]);
    }
  }
  #pragma unroll
  for (int mt = 0; mt < 4; mt++){
    int gm0 = bm + warpM*64 + mt*16 + g;
    #pragma unroll
    for (int nt = 0; nt < 4; nt++){
      int gn = bn + warpN*32 + nt*8 + 2*t4;
      float e0 = b1[gn] + b2[gn], e1 = b1[gn+1] + b2[gn+1];
      C[(size_t)gm0*G4 + gn]         = acc[mt][nt][0] + e0;
      C[(size_t)gm0*G4 + gn + 1]     = acc[mt][nt][1] + e1;
      C[(size_t)(gm0+8)*G4 + gn]     = acc[mt][nt][2] + e0;
      C[(size_t)(gm0+8)*G4 + gn + 1] = acc[mt][nt][3] + e1;
    }
  }
}

// =======================================================================
// Persistent LSTM: all 20 steps in ONE kernel, 88 blocks, grid barrier.
// Double-buffered smem: ONE __syncthreads per K-iteration.
// =======================================================================
__device__ __forceinline__ void grid_sync(unsigned target){
  __syncthreads();
  if (threadIdx.x == 0){
    __threadfence();
    atomicAdd(&g_bar, 1u);
    while (atomicAdd(&g_bar, 0u) < target) {}
    __threadfence();
  }
  __syncthreads();
}

#define LS_A_STG 3072u     // 64*24*2 bytes per stage
#define LS_B_STG 12288u    // 256*24*2 bytes per stage

__global__ __launch_bounds__(256) void lstm_persist()
{
  const int n0 = (blockIdx.x & 7) * 64;
  const int rt = blockIdx.x >> 3;            // 0..10
  const int tid = threadIdx.x, lane = tid & 31, wid = tid >> 5;
  const int warpM = wid & 3, warpN = wid >> 2;
  const int g8 = lane >> 2, t4 = lane & 3;

  __shared__ __align__(16) uint16_t sA[2][64][24];
  __shared__ __align__(16) uint16_t sB[2][256][24];
  const uint32_t sAu = (uint32_t)__cvta_generic_to_shared(&sA[0][0][0]);
  const uint32_t sBu = (uint32_t)__cvta_generic_to_shared(&sB[0][0][0]);
  const int bmat = lane >> 3;
  const uint32_t aOff = ((uint32_t)(warpM*16 + (lane & 15))*24 + (uint32_t)(lane >> 4)*8)*2;
  const uint32_t bOff = ((uint32_t)(warpN*32 + ((bmat >> 1)*8) + (lane & 7))*24
                        + (uint32_t)(bmat & 1)*8)*2;
  const int arow = tid >> 1, ak8 = (tid & 1)*8;
  const int rbr = tid >> 1;                  // B loader row pair base
  const int bk8 = (tid & 1)*8;

  for (int j = 0; j < NSEQ; j++){
    const int p = j & 1;
    const int tf = (j + 2) >> 1;
    int dir, bm, rowLim;
    if (rt < tf){ dir = 0; bm = rt*64;                   rowLim = (j+1)*BSZ; }
    else        { dir = 1; bm = j*BSZ + (rt - tf)*64;    rowLim = NSEQ*BSZ; }

    const __half* __restrict__ Ain = g_H16[dir][p];
    const __half* __restrict__ W = g_W16[dir];
    const int gr = bm + arow;
    const bool aok = (gr < rowLim);
    const int wrow0 = (rbr >> 6)*HID + n0 + (rbr & 63);
    const int wrow1 = ((rbr + 128) >> 6)*HID + n0 + ((rbr + 128) & 63);

    float acc[4][4][4] = {};
    uint4 ra, rb0, rb1;
    // prologue: k=0
    if (tid < 128)
      ra = aok ? *(const uint4*)(Ain + (size_t)gr*HID + ak8) : make_uint4(0,0,0,0);
    rb0 = *(const uint4*)(W + (size_t)wrow0*HID + bk8);
    rb1 = *(const uint4*)(W + (size_t)wrow1*HID + bk8);
    if (tid < 128) *(uint4*)&sA[0][arow][ak8] = ra;
    *(uint4*)&sB[0][rbr][bk8] = rb0;
    *(uint4*)&sB[0][rbr + 128][bk8] = rb1;
    __syncthreads();

    #pragma unroll 4
    for (int it = 0; it < 32; it++){
      const int s = it & 1;
      if (it < 31){
        int kn = (it + 1)*16;
        if (tid < 128)
          ra = aok ? *(const uint4*)(Ain + (size_t)gr*HID + kn + ak8) : make_uint4(0,0,0,0);
        rb0 = *(const uint4*)(W + (size_t)wrow0*HID + kn + bk8);
        rb1 = *(const uint4*)(W + (size_t)wrow1*HID + kn + bk8);
      }
      // compute stage s
      uint32_t af[4];
      ldsm4(af, sAu + (uint32_t)s*LS_A_STG + aOff);
      #pragma unroll
      for (int g = 0; g < 4; g++){
        uint32_t bq[2][4];
        uint32_t base = sBu + (uint32_t)s*LS_B_STG + (uint32_t)g*64*48 + bOff;
        ldsm4(bq[0], base);
        ldsm4(bq[1], base + 16*48);
        #pragma unroll
        for (int nt = 0; nt < 4; nt++)
          mma16h(acc[g][nt], af, &bq[nt>>1][(nt&1)*2]);
      }
      if (it < 31){
        const int d = s ^ 1;
        if (tid < 128) *(uint4*)&sA[d][arow][ak8] = ra;
        *(uint4*)&sB[d][rbr][bk8] = rb0;
        *(uint4*)&sB[d][rbr + 128][bk8] = rb1;
        __syncthreads();
      }
    }

    // ---- epilogue ----
    {
      const float* __restrict__ X = g_X[dir];
      float* __restrict__ C = g_C[dir];
      __half* __restrict__ Hn = g_H16[dir][p^1];
      float* __restrict__ F  = dir ? g_Fb  : g_Ff;
      __half* __restrict__ F16 = dir ? g_FB16 : g_FF16;

      #pragma unroll
      for (int rr = 0; rr < 2; rr++){
        int gm = bm + warpM*16 + g8 + rr*8;
        if (gm >= rowLim) continue;
        int chain = gm >> 5, b = gm & 31;
        int t = dir ? (chain - j) : j;
        size_t xrow = (size_t)(b*NSEQ + t)*G4;
        size_t fbase;
        bool first;
        if (dir == 0){ fbase = ((size_t)(b*NSEQ + chain)*NSEQ + j)*HID; first = (j == chain); }
        else         { fbase = ((size_t)(b*NSEQ + chain)*NSEQ + t)*HID; first = (t == chain); }
        #pragma unroll
        for (int nt = 0; nt < 4; nt++){
          #pragma unroll
          for (int cc = 0; cc < 2; cc++){
            int n = n0 + warpN*32 + nt*8 + t4*2 + cc;
            int ai = rr*2 + cc;
            float gi = acc[0][nt][ai] + X[xrow + n];
            float gf = acc[1][nt][ai] + X[xrow + 512 + n];
            float gc = acc[2][nt][ai] + X[xrow + 1024 + n];
            float go = acc[3][nt][ai] + X[xrow + 1536 + n];
            size_t si = (size_t)gm*HID + n;
            float c = sigm(gf)*C[si] + sigm(gi)*tanhf(gc);
            float h = sigm(go)*tanhf(c);
            C[si] = c;
            Hn[si] = __float2half(h);
            float prev = first ? 0.f : F[fbase + n + (dir ? (int)HID : -(int)HID)];
            float v = prev + h;
            F[fbase + n]   = v;
            F16[fbase + n] = __float2half(v);
          }
        }
      }
    }
    grid_sync((unsigned)(LSTM_BLOCKS*(j+1)));
  }
}

// =======================================================================
// out GEMM + fused L2 normalize, double-buffered smem (ONE sync/iter).
// BM=64, BN=256 (= one SEM group), 256 threads = 8 warps (2M x 4N).
// grid (30, 95).
// =======================================================================
#define OG_A_STG 5120u     // 64*40*2 bytes per stage
#define OG_B_STG 20480u    // 256*40*2 bytes per stage

__global__ __launch_bounds__(256) void out_gemm_fused(const float* __restrict__ bout,
                                                      float* __restrict__ out)
{
  __shared__ __align__(16) __half sA[2][64][40];
  __shared__ __align__(16) __half sB[2][256][40];
  __shared__ int offF[64], offB[64], cnt[64];
  __shared__ float ssb[4][64];
  const int tid = threadIdx.x, lane = tid & 31, wid = tid >> 5;
  const int warpM = wid >> 2, warpN = wid & 3;
  const int g = lane >> 2, t4 = lane & 3;
  const int bm = blockIdx.y*64, bn = blockIdx.x*256;

  if (tid < 64){
    int gm = bm + tid;
    int b = gm / NPAIR, p = gm % NPAIR;
    offF[tid] = (b*NSEQ*NSEQ + g_psF[p])*HID;
    offB[tid] = (b*NSEQ*NSEQ + g_psB[p])*HID;
    cnt[tid]  = g_pcnt[p];
  }
  __syncthreads();

  const uint32_t sAu = (uint32_t)__cvta_generic_to_shared(&sA[0][0][0]);
  const uint32_t sBu = (uint32_t)__cvta_generic_to_shared(&sB[0][0][0]);
  const int bmat = lane >> 3;
  const uint32_t aOff = ((uint32_t)(warpM*32 + (lane & 15))*40 + (uint32_t)(lane >> 4)*8)*2;
  const uint32_t bOff = ((uint32_t)(warpN*64 + ((bmat >> 1)*8) + (lane & 7))*40
                        + (uint32_t)(bmat & 1)*8)*2;

  // loaders: A 64x32 halves -> 1 uint4/thread; B 256x32 -> 4 uint4/thread
  const int arow = tid >> 2, ak = (tid & 3)*8;
  const int aF = offF[arow], aB = offB[arow];
  uint4 ra, rbv[4];
  // prologue: k=0 -> stage 0
  ra = *(const uint4*)(g_FF16 + aF + ak);
  #pragma unroll
  for (int s = 0; s < 4; s++){
    int idx = tid + s*256;
    int br = idx >> 2, bk = (idx & 3)*8;
    rbv[s] = *(const uint4*)(g_WO16 + (size_t)(bn + br)*(2*HID) + bk);
  }
  *(uint4*)&sA[0][arow][ak] = ra;
  #pragma unroll
  for (int s = 0; s < 4; s++){
    int idx = tid + s*256;
    int br = idx >> 2, bk = (idx & 3)*8;
    *(uint4*)&sB[0][br][bk] = rbv[s];
  }
  __syncthreads();

  float acc[2][8][4] = {};
  #pragma unroll 2
  for (int it = 0; it < 32; it++){
    const int stg = it & 1;
    if (it < 31){
      int k = (it + 1)*32 + ak;
      const __half* srcA = (k < HID) ? (g_FF16 + aF + k) : (g_FB16 + aB + k - HID);
      ra = *(const uint4*)srcA;
      #pragma unroll
      for (int s = 0; s < 4; s++){
        int idx = tid + s*256;
        int br = idx >> 2, bk = (idx & 3)*8;
        rbv[s] = *(const uint4*)(g_WO16 + (size_t)(bn + br)*(2*HID) + (it + 1)*32 + bk);
      }
    }
    // compute stage stg
    #pragma unroll
    for (int ks = 0; ks < 32; ks += 16){
      uint32_t a[2][4];
      ldsm4(a[0], sAu + (uint32_t)stg*OG_A_STG + aOff + (uint32_t)ks*2);
      ldsm4(a[1], sAu + (uint32_t)stg*OG_A_STG + aOff + 16*80 + (uint32_t)ks*2);
      #pragma unroll
      for (int q = 0; q < 4; q++){
        uint32_t bq[4];
        ldsm4(bq, sBu + (uint32_t)stg*OG_B_STG + bOff + (uint32_t)q*16*80 + (uint32_t)ks*2);
        #pragma unroll
        for (int mt = 0; mt < 2; mt++){
          mma16h(acc[mt][q*2],     a[mt], &bq[0]);
          mma16h(acc[mt][q*2 + 1], a[mt], &bq[2]);
        }
      }
    }
    if (it < 31){
      const int d = stg ^ 1;
      *(uint4*)&sA[d][arow][ak] = ra;
      #pragma unroll
      for (int s = 0; s < 4; s++){
        int idx = tid + s*256;
        int br = idx >> 2, bk = (idx & 3)*8;
        *(uint4*)&sB[d][br][bk] = rbv[s];
      }
      __syncthreads();
    }
  }

  // ---- epilogue: + cnt*bias, fused L2-normalize over the 256-wide group ----
  const int r0 = warpM*32 + g;
  float ssr[2][2] = {};
  #pragma unroll
  for (int mt = 0; mt < 2; mt++){
    int rl = r0 + mt*16;
    float c0 = (float)cnt[rl], c1 = (float)cnt[rl + 8];
    #pragma unroll
    for (int nt = 0; nt < 8; nt++){
      int gn = bn + warpN*64 + nt*8 + 2*t4;
      float b0 = bout[gn], b1 = bout[gn + 1];
      acc[mt][nt][0] += c0*b0;  acc[mt][nt][1] += c0*b1;
      acc[mt][nt][2] += c1*b0;  acc[mt][nt][3] += c1*b1;
      ssr[mt][0] += acc[mt][nt][0]*acc[mt][nt][0] + acc[mt][nt][1]*acc[mt][nt][1];
      ssr[mt][1] += acc[mt][nt][2]*acc[mt][nt][2] + acc[mt][nt][3]*acc[mt][nt][3];
    }
  }
  #pragma unroll
  for (int mt = 0; mt < 2; mt++)
    #pragma unroll
    for (int pq = 0; pq < 2; pq++){
      ssr[mt][pq] += __shfl_xor_sync(0xffffffffu, ssr[mt][pq], 1);
      ssr[mt][pq] += __shfl_xor_sync(0xffffffffu, ssr[mt][pq], 2);
    }
  __syncthreads();   // stage buffers done; reuse barrier before ssb writes is implicit-safe
  if (t4 == 0){
    ssb[warpN][r0]      = ssr[0][0];
    ssb[warpN][r0 + 8]  = ssr[0][1];
    ssb[warpN][r0 + 16] = ssr[1][0];
    ssb[warpN][r0 + 24] = ssr[1][1];
  }
  __syncthreads();
  #pragma unroll
  for (int mt = 0; mt < 2; mt++){
    #pragma unroll
    for (int pq = 0; pq < 2; pq++){
      int rl = r0 + mt*16 + pq*8;
      int gm = bm + rl;
      float tot = ssb[0][rl] + ssb[1][rl] + ssb[2][rl] + ssb[3][rl];
      float sc = 1.f / fmaxf(sqrtf(tot), 1e-12f);
      #pragma unroll
      for (int nt = 0; nt < 8; nt++){
        int gn = bn + warpN*64 + nt*8 + 2*t4;
        float2 v;
        v.x = acc[mt][nt][pq*2]     * sc;
        v.y = acc[mt][nt][pq*2 + 1] * sc;
        *(float2*)(out + (size_t)gm*NOUT + gn) = v;
      }
    }
  }
}

// ---------------- launcher ----------------
extern "C" void kernel_launch(void* const* d_in, const int* in_sizes, int n_in,
                              void* d_out, int out_size)
{
  const int*   captions = (const int*)  d_in[1];
  const int*   lengths  = (const int*)  d_in[2];
  const float* emb      = (const float*)d_in[3];
  const float* w_ih_f   = (const float*)d_in[4];
  const float* w_hh_f   = (const float*)d_in[5];
  const float* b_ih_f   = (const float*)d_in[6];
  const float* b_hh_f   = (const float*)d_in[7];
  const float* w_ih_b   = (const float*)d_in[8];
  const float* w_hh_b   = (const float*)d_in[9];
  const float* b_ih_b   = (const float*)d_in[10];
  const float* b_hh_b   = (const float*)d_in[11];
  const float* w_out    = (const float*)d_in[12];
  const float* b_out    = (const float*)d_in[13];
  float* out = (float*)d_out;

  zero_state_kernel<<<(4*SB + 255)/256, 256>>>();
  setup_pairs_kernel<<<1, 256>>>();
  embed_kernel<<<BSZ*NSEQ, 256>>>(captions, lengths, emb);
  wconv_kernel<<<(G4*HID + 255)/256, 256>>>(w_ih_f, w_ih_b, w_hh_f, w_hh_b);
  wout16_kernel<<<(NOUT*2*HID + 255)/256, 256>>>(w_out);

  // input projections (single-pass fp16, both dirs)
  gemm16_bias<<<dim3(G4/128, (BSZ*NSEQ)/128, 2), 256>>>(b_ih_f, b_hh_f, b_ih_b, b_hh_b);

  // all 20 LSTM steps in one persistent kernel
  lstm_persist<<<LSTM_BLOCKS, 256>>>();

  // final projection + bias + fused per-group L2 normalize
  out_gemm_fused<<<dim3(NOUT/256, MROWS/64), 256>>>(b_out, out);
}

// round 14
// speedup vs baseline: 1.0543x; 1.0543x over previous
#include <cuda_runtime.h>
#include <cuda_fp16.h>
#include <stdint.h>

#define BSZ 32
#define NSEQ 20
#define DIM 512
#define HID 512
#define G4 2048          // 4*HID
#define NOUT 7680        // NT*SEM
#define SEM 256
#define NPAIR 190
#define MROWS (BSZ*NPAIR)   // 6080
#define SB (NSEQ*BSZ*HID)   // 640*512 per plane
#define FSZ (BSZ*NSEQ*NSEQ*HID)
#define LSTM_BLOCKS 88

// ---------------- device scratch ----------------
__device__ __half g_WV16[BSZ*NSEQ*DIM];        // masked word vectors fp16
__device__ float g_X[2][BSZ*NSEQ*G4];          // input projections (f, b)
__device__ __half g_H16[2][2][SB];             // [dir][parity] hidden (fp16)
__device__ float g_C[2][SB];                   // cell state
__device__ __half g_WI16[2][G4*DIM];           // W_ih fp16 (f, b)
__device__ __half g_W16[2][G4*HID];            // W_hh fp16 (f, b)
__device__ float g_Ff[FSZ];                    // fp32 cumulative sums
__device__ float g_Fb[FSZ];
__device__ __half g_FF16[FSZ];                 // fp16 cumsum planes (out GEMM)
__device__ __half g_FB16[FSZ];
__device__ __half g_WO16[NOUT*2*HID];          // fp16 w_out
__device__ int   g_psF[NPAIR];
__device__ int   g_psB[NPAIR];
__device__ int   g_pcnt[NPAIR];
__device__ unsigned g_bar;

__device__ __forceinline__ float sigm(float x){ return 1.f/(1.f+__expf(-x)); }

__device__ __forceinline__ void mma16h(float c[4], const uint32_t a[4], const uint32_t b[2]){
  asm volatile("mma.sync.aligned.m16n8k16.row.col.f32.f16.f16.f32 "
      "{%0,%1,%2,%3}, {%4,%5,%6,%7}, {%8,%9}, {%0,%1,%2,%3};\n"
      : "+f"(c[0]), "+f"(c[1]), "+f"(c[2]), "+f"(c[3])
      : "r"(a[0]), "r"(a[1]), "r"(a[2]), "r"(a[3]), "r"(b[0]), "r"(b[1]));
}
__device__ __forceinline__ void ldsm4(uint32_t r[4], uint32_t saddr){
  asm volatile("ldmatrix.sync.aligned.m8n8.x4.shared.b16 {%0,%1,%2,%3}, [%4];"
      : "=r"(r[0]), "=r"(r[1]), "=r"(r[2]), "=r"(r[3]) : "r"(saddr));
}
__device__ __forceinline__ void cpa16(uint32_t dst, const void* src){
  asm volatile("cp.async.cg.shared.global [%0], [%1], 16;" :: "r"(dst), "l"(src) : "memory");
}
#define CPA_COMMIT() asm volatile("cp.async.commit_group;" ::: "memory")
#define CPA_WAIT1()  asm volatile("cp.async.wait_group 1;" ::: "memory")
#define CPA_WAIT0()  asm volatile("cp.async.wait_group 0;" ::: "memory")

// ---------------- small setup kernels ----------------
__global__ void zero_state_kernel(){
  int i = blockIdx.x*blockDim.x + threadIdx.x;
  if (i < 4*SB) (&g_H16[0][0][0])[i] = __float2half(0.f);
  if (i < 2*SB) (&g_C[0][0])[i] = 0.f;
}

// convert all weights to fp16 in ONE launch
__global__ void wcvt_kernel(const float* __restrict__ wih_f, const float* __restrict__ wih_b,
                            const float* __restrict__ whh_f, const float* __restrict__ whh_b,
                            const float* __restrict__ wout){
  int i = blockIdx.x*blockDim.x + threadIdx.x;
  if (i < G4*HID){
    g_WI16[0][i] = __float2half(wih_f[i]);
    g_WI16[1][i] = __float2half(wih_b[i]);
    g_W16[0][i]  = __float2half(whh_f[i]);
    g_W16[1][i]  = __float2half(whh_b[i]);
  }
  if (i < NOUT*2*HID) g_WO16[i] = __float2half(wout[i]);
}

__global__ void setup_pairs_kernel(){
  if (threadIdx.x == 0) g_bar = 0;           // reset grid barrier each replay
  int p = threadIdx.x;
  if (p >= NPAIR) return;
  int cum = 0, k = 1, s = 0;
  for (int kk = 1; kk < NSEQ; kk++){
    int c = NSEQ - kk;
    if (p < cum + c){ k = kk; s = p - cum; break; }
    cum += c;
  }
  int e = s + k;
  g_psF[p] = s*NSEQ + e;
  g_psB[p] = e*NSEQ + s;
  g_pcnt[p] = k + 1;
}

__global__ void embed_kernel(const int* __restrict__ cap, const int* __restrict__ len,
                             const float* __restrict__ emb){
  int bt = blockIdx.x; int b = bt/NSEQ, t = bt%NSEQ;
  int tok = cap[bt];
  float m = (t < len[b]) ? 1.f : 0.f;
  const float* src = emb + (size_t)tok*DIM;
  for (int n = threadIdx.x; n < DIM; n += blockDim.x)
    g_WV16[bt*DIM + n] = __float2half(m * src[n]);
}

// =======================================================================
// FP16 projection GEMM: X[dir] = WV16 @ WI16[dir]^T + (b_ih + b_hh)
// =======================================================================
__global__ __launch_bounds__(256) void gemm16_bias(
    const float* __restrict__ bif, const float* __restrict__ bhf,
    const float* __restrict__ bib, const float* __restrict__ bhb)
{
  const int dir = blockIdx.z;
  const __half* __restrict__ A = g_WV16;
  const __half* __restrict__ B = g_WI16[dir];
  const float* __restrict__ b1 = dir ? bib : bif;
  const float* __restrict__ b2 = dir ? bhb : bhf;
  float* __restrict__ C = g_X[dir];

  __shared__ __align__(16) __half sA[128][40];
  __shared__ __align__(16) __half sB[128][40];
  const int tid = threadIdx.x, lane = tid & 31, wid = tid >> 5;
  const int warpM = wid >> 2, warpN = wid & 3;
  const int g = lane >> 2, t4 = lane & 3;
  const int bm = blockIdx.y*128, bn = blockIdx.x*128;

  const uint32_t sAu = (uint32_t)__cvta_generic_to_shared(&sA[0][0]);
  const uint32_t sBu = (uint32_t)__cvta_generic_to_shared(&sB[0][0]);
  const int bmat = lane >> 3;
  const uint32_t aOff = ((uint32_t)(warpM*64 + (lane & 15))*40 + (uint32_t)(lane >> 4)*8)*2;
  const uint32_t bOff = ((uint32_t)(warpN*32 + ((bmat >> 1)*8) + (lane & 7))*40
                        + (uint32_t)(bmat & 1)*8)*2;

  const int arow = tid >> 1, ak = (tid & 1)*16;
  uint4 ra[2], rb[2];
  {
    const __half* srcA = A + (size_t)(bm + arow)*DIM + ak;
    ra[0] = *(const uint4*)srcA;
    ra[1] = *(const uint4*)(srcA + 8);
    const __half* srcB = B + (size_t)(bn + arow)*DIM + ak;
    rb[0] = *(const uint4*)srcB;
    rb[1] = *(const uint4*)(srcB + 8);
  }

  float acc[4][4][4] = {};
  for (int k0 = 0; k0 < DIM; k0 += 32){
    __syncthreads();
    *(uint4*)&sA[arow][ak]     = ra[0];
    *(uint4*)&sA[arow][ak + 8] = ra[1];
    *(uint4*)&sB[arow][ak]     = rb[0];
    *(uint4*)&sB[arow][ak + 8] = rb[1];
    __syncthreads();
    if (k0 + 32 < DIM){
      const __half* srcA = A + (size_t)(bm + arow)*DIM + k0 + 32 + ak;
      ra[0] = *(const uint4*)srcA;
      ra[1] = *(const uint4*)(srcA + 8);
      const __half* srcB = B + (size_t)(bn + arow)*DIM + k0 + 32 + ak;
      rb[0] = *(const uint4*)srcB;
      rb[1] = *(const uint4*)(srcB + 8);
    }
    #pragma unroll
    for (int ks = 0; ks < 32; ks += 16){
      uint32_t a[4][4], bq[2][4];
      #pragma unroll
      for (int mt = 0; mt < 4; mt++)
        ldsm4(a[mt], sAu + aOff + (uint32_t)mt*16*80 + (uint32_t)ks*2);
      ldsm4(bq[0], sBu + bOff + (uint32_t)ks*2);
      ldsm4(bq[1], sBu + bOff + 16*80 + (uint32_t)ks*2);
      #pragma unroll
      for (int mt = 0; mt < 4; mt++)
        #pragma unroll
        for (int nt = 0; nt < 4; nt++)
          mma16h(acc[mt][nt], a[mt], &bq[nt>>1][(nt&1)*2]);
    }
  }
  #pragma unroll
  for (int mt = 0; mt < 4; mt++){
    int gm0 = bm + warpM*64 + mt*16 + g;
    #pragma unroll
    for (int nt = 0; nt < 4; nt++){
      int gn = bn + warpN*32 + nt*8 + 2*t4;
      float e0 = b1[gn] + b2[gn], e1 = b1[gn+1] + b2[gn+1];
      C[(size_t)gm0*G4 + gn]         = acc[mt][nt][0] + e0;
      C[(size_t)gm0*G4 + gn + 1]     = acc[mt][nt][1] + e1;
      C[(size_t)(gm0+8)*G4 + gn]     = acc[mt][nt][2] + e0;
      C[(size_t)(gm0+8)*G4 + gn + 1] = acc[mt][nt][3] + e1;
    }
  }
}

// =======================================================================
// Persistent LSTM (R12 structure): 20 steps, 88 blocks, grid barrier.
// =======================================================================
__device__ __forceinline__ void grid_sync(unsigned target){
  __syncthreads();
  if (threadIdx.x == 0){
    __threadfence();
    atomicAdd(&g_bar, 1u);
    while (atomicAdd(&g_bar, 0u) < target) {}
    __threadfence();
  }
  __syncthreads();
}

__global__ __launch_bounds__(256) void lstm_persist()
{
  const int n0 = (blockIdx.x & 7) * 64;
  const int rt = blockIdx.x >> 3;            // 0..10
  const int tid = threadIdx.x, lane = tid & 31, wid = tid >> 5;
  const int warpM = wid & 3, warpN = wid >> 2;
  const int g8 = lane >> 2, t4 = lane & 3;

  __shared__ __align__(16) uint16_t sA[64][24];    // 3072 B
  __shared__ __align__(16) uint16_t sB[256][24];   // 12288 B
  const uint32_t sAu = (uint32_t)__cvta_generic_to_shared(&sA[0][0]);
  const uint32_t sBu = (uint32_t)__cvta_generic_to_shared(&sB[0][0]);
  const int bmat = lane >> 3;
  const uint32_t aOff = ((uint32_t)(warpM*16 + (lane & 15))*24 + (uint32_t)(lane >> 4)*8)*2;
  const uint32_t bOff = ((uint32_t)(warpN*32 + ((bmat >> 1)*8) + (lane & 7))*24
                        + (uint32_t)(bmat & 1)*8)*2;
  const int arow = tid >> 1, ak8 = (tid & 1)*8;

  for (int j = 0; j < NSEQ; j++){
    const int p = j & 1;
    const int tf = (j + 2) >> 1;             // ceil((j+1)/2) forward tiles
    int dir, bm, rowLim;
    if (rt < tf){ dir = 0; bm = rt*64;                   rowLim = (j+1)*BSZ; }
    else        { dir = 1; bm = j*BSZ + (rt - tf)*64;    rowLim = NSEQ*BSZ; }

    const __half* __restrict__ Ain = g_H16[dir][p];
    const __half* __restrict__ W = g_W16[dir];

    float acc[4][4][4] = {};
    uint4 ra; uint4 rb[2];
    {
      int gr = bm + arow;
      if (tid < 128)
        ra = (gr < rowLim) ? *(const uint4*)(Ain + (size_t)gr*HID + ak8)
                           : make_uint4(0,0,0,0);
      #pragma unroll
      for (int s = 0; s < 2; s++){
        int i = tid + s*256;
        int rbr = i >> 1, k8 = (i & 1)*8;
        int wrow = (rbr >> 6)*HID + n0 + (rbr & 63);
        rb[s] = *(const uint4*)(W + (size_t)wrow*HID + k8);
      }
    }

    for (int k0 = 0; k0 < HID; k0 += 16){
      __syncthreads();
      if (tid < 128) *(uint4*)&sA[arow][ak8] = ra;
      #pragma unroll
      for (int s = 0; s < 2; s++){
        int i = tid + s*256;
        int rbr = i >> 1, k8 = (i & 1)*8;
        *(uint4*)&sB[rbr][k8] = rb[s];
      }
      __syncthreads();
      if (k0 + 16 < HID){
        int kn = k0 + 16;
        if (tid < 128){
          int gr = bm + arow;
          ra = (gr < rowLim) ? *(const uint4*)(Ain + (size_t)gr*HID + kn + ak8)
                             : make_uint4(0,0,0,0);
        }
        #pragma unroll
        for (int s = 0; s < 2; s++){
          int i = tid + s*256;
          int rbr = i >> 1, k8 = (i & 1)*8;
          int wrow = (rbr >> 6)*HID + n0 + (rbr & 63);
          rb[s] = *(const uint4*)(W + (size_t)wrow*HID + kn + k8);
        }
      }
      uint32_t af[4];
      ldsm4(af, sAu + aOff);
      #pragma unroll
      for (int g = 0; g < 4; g++){
        uint32_t bq[2][4];
        uint32_t base = sBu + (uint32_t)g*64*48 + bOff;
        ldsm4(bq[0], base);
        ldsm4(bq[1], base + 16*48);
        #pragma unroll
        for (int nt = 0; nt < 4; nt++)
          mma16h(acc[g][nt], af, &bq[nt>>1][(nt&1)*2]);
      }
    }

    // ---- epilogue ----
    {
      const float* __restrict__ X = g_X[dir];
      float* __restrict__ C = g_C[dir];
      __half* __restrict__ Hn = g_H16[dir][p^1];
      float* __restrict__ F  = dir ? g_Fb  : g_Ff;
      __half* __restrict__ F16 = dir ? g_FB16 : g_FF16;

      #pragma unroll
      for (int rr = 0; rr < 2; rr++){
        int gm = bm + warpM*16 + g8 + rr*8;
        if (gm >= rowLim) continue;
        int chain = gm >> 5, b = gm & 31;
        int t = dir ? (chain - j) : j;
        size_t xrow = (size_t)(b*NSEQ + t)*G4;
        size_t fbase;
        bool first;
        if (dir == 0){ fbase = ((size_t)(b*NSEQ + chain)*NSEQ + j)*HID; first = (j == chain); }
        else         { fbase = ((size_t)(b*NSEQ + chain)*NSEQ + t)*HID; first = (t == chain); }
        #pragma unroll
        for (int nt = 0; nt < 4; nt++){
          #pragma unroll
          for (int cc = 0; cc < 2; cc++){
            int n = n0 + warpN*32 + nt*8 + t4*2 + cc;
            int ai = rr*2 + cc;
            float gi = acc[0][nt][ai] + X[xrow + n];
            float gf = acc[1][nt][ai] + X[xrow + 512 + n];
            float gc = acc[2][nt][ai] + X[xrow + 1024 + n];
            float go = acc[3][nt][ai] + X[xrow + 1536 + n];
            size_t si = (size_t)gm*HID + n;
            float c = sigm(gf)*C[si] + sigm(gi)*tanhf(gc);
            float h = sigm(go)*tanhf(c);
            C[si] = c;
            Hn[si] = __float2half(h);
            float prev = first ? 0.f : F[fbase + n + (dir ? (int)HID : -(int)HID)];
            float v = prev + h;
            F[fbase + n]   = v;
            F16[fbase + n] = __float2half(v);
          }
        }
      }
    }
    grid_sync((unsigned)(LSTM_BLOCKS*(j+1)));
  }
}

// =======================================================================
// out GEMM + fused L2 normalize: cp.async 3-stage pipeline, ONE sync/iter.
// BM=64, BN=256 (= one SEM group), 256 threads = 8 warps (2M x 4N).
// grid (30, 95).
// =======================================================================
#define OGA 5120u      // A stage stride: 64*40*2
#define OGB 20480u     // B stage stride: 256*40*2

__global__ __launch_bounds__(256) void out_gemm_fused(const float* __restrict__ bout,
                                                      float* __restrict__ out)
{
  __shared__ __align__(16) __half sA[3][64][40];
  __shared__ __align__(16) __half sB[3][256][40];
  __shared__ int offF[64], offB[64], cnt[64];
  __shared__ float ssb[4][64];
  const int tid = threadIdx.x, lane = tid & 31, wid = tid >> 5;
  const int warpM = wid >> 2, warpN = wid & 3;
  const int g = lane >> 2, t4 = lane & 3;
  const int bm = blockIdx.y*64, bn = blockIdx.x*256;

  if (tid < 64){
    int gm = bm + tid;
    int b = gm / NPAIR, p = gm % NPAIR;
    offF[tid] = (b*NSEQ*NSEQ + g_psF[p])*HID;
    offB[tid] = (b*NSEQ*NSEQ + g_psB[p])*HID;
    cnt[tid]  = g_pcnt[p];
  }
  __syncthreads();

  const uint32_t sAu = (uint32_t)__cvta_generic_to_shared(&sA[0][0][0]);
  const uint32_t sBu = (uint32_t)__cvta_generic_to_shared(&sB[0][0][0]);
  const int bmat = lane >> 3;
  const uint32_t aOff = ((uint32_t)(warpM*32 + (lane & 15))*40 + (uint32_t)(lane >> 4)*8)*2;
  const uint32_t bOff = ((uint32_t)(warpN*64 + ((bmat >> 1)*8) + (lane & 7))*40
                        + (uint32_t)(bmat & 1)*8)*2;

  // loader coords: A 64x32 halves -> 1 x 16B/thread; B 256x32 -> 4 x 16B/thread
  const int arow = tid >> 2, ak = (tid & 3)*8;
  const int aF = offF[arow], aB = offB[arow];
  const uint32_t aDst = sAu + ((uint32_t)arow*40 + (uint32_t)ak)*2;
  uint32_t bDst[4];
  const __half* bSrc[4];
  #pragma unroll
  for (int s = 0; s < 4; s++){
    int idx = tid + s*256;
    int br = idx >> 2, bk = (idx & 3)*8;
    bDst[s] = sBu + ((uint32_t)br*40 + (uint32_t)bk)*2;
    bSrc[s] = g_WO16 + (size_t)(bn + br)*(2*HID) + bk;
  }

  // issue loads for K-iteration `it` into stage `stg`
  #define OG_ISSUE(stg, it) do{                                               \
    int k_ = (it)*32 + ak;                                                    \
    const __half* srcA_ = (k_ < HID) ? (g_FF16 + aF + k_)                     \
                                     : (g_FB16 + aB + k_ - HID);              \
    cpa16(aDst + (uint32_t)(stg)*OGA, srcA_);                                 \
    _Pragma("unroll")                                                         \
    for (int s_ = 0; s_ < 4; s_++)                                            \
      cpa16(bDst[s_] + (uint32_t)(stg)*OGB, bSrc[s_] + (it)*32);              \
    CPA_COMMIT();                                                             \
  } while(0)

  OG_ISSUE(0, 0);
  OG_ISSUE(1, 1);

  float acc[2][8][4] = {};
  int stg = 0;
  for (int it = 0; it < 32; it++){
    if (it >= 30) CPA_WAIT0(); else CPA_WAIT1();
    __syncthreads();
    if (it + 2 < 32){
      int ns = stg + 2; if (ns >= 3) ns -= 3;
      OG_ISSUE(ns, it + 2);
    }
    // compute stage stg
    #pragma unroll
    for (int ks = 0; ks < 32; ks += 16){
      uint32_t a[2][4];
      ldsm4(a[0], sAu + (uint32_t)stg*OGA + aOff + (uint32_t)ks*2);
      ldsm4(a[1], sAu + (uint32_t)stg*OGA + aOff + 16*80 + (uint32_t)ks*2);
      #pragma unroll
      for (int q = 0; q < 4; q++){
        uint32_t bq[4];
        ldsm4(bq, sBu + (uint32_t)stg*OGB + bOff + (uint32_t)q*16*80 + (uint32_t)ks*2);
        #pragma unroll
        for (int mt = 0; mt < 2; mt++){
          mma16h(acc[mt][q*2],     a[mt], &bq[0]);
          mma16h(acc[mt][q*2 + 1], a[mt], &bq[2]);
        }
      }
    }
    if (++stg >= 3) stg = 0;
  }

  // ---- epilogue: + cnt*bias, fused L2-normalize over the 256-wide group ----
  const int r0 = warpM*32 + g;
  float ssr[2][2] = {};
  #pragma unroll
  for (int mt = 0; mt < 2; mt++){
    int rl = r0 + mt*16;
    float c0 = (float)cnt[rl], c1 = (float)cnt[rl + 8];
    #pragma unroll
    for (int nt = 0; nt < 8; nt++){
      int gn = bn + warpN*64 + nt*8 + 2*t4;
      float b0 = bout[gn], b1 = bout[gn + 1];
      acc[mt][nt][0] += c0*b0;  acc[mt][nt][1] += c0*b1;
      acc[mt][nt][2] += c1*b0;  acc[mt][nt][3] += c1*b1;
      ssr[mt][0] += acc[mt][nt][0]*acc[mt][nt][0] + acc[mt][nt][1]*acc[mt][nt][1];
      ssr[mt][1] += acc[mt][nt][2]*acc[mt][nt][2] + acc[mt][nt][3]*acc[mt][nt][3];
    }
  }
  #pragma unroll
  for (int mt = 0; mt < 2; mt++)
    #pragma unroll
    for (int pq = 0; pq < 2; pq++){
      ssr[mt][pq] += __shfl_xor_sync(0xffffffffu, ssr[mt][pq], 1);
      ssr[mt][pq] += __shfl_xor_sync(0xffffffffu, ssr[mt][pq], 2);
    }
  __syncthreads();
  if (t4 == 0){
    ssb[warpN][r0]      = ssr[0][0];
    ssb[warpN][r0 + 8]  = ssr[0][1];
    ssb[warpN][r0 + 16] = ssr[1][0];
    ssb[warpN][r0 + 24] = ssr[1][1];
  }
  __syncthreads();
  #pragma unroll
  for (int mt = 0; mt < 2; mt++){
    #pragma unroll
    for (int pq = 0; pq < 2; pq++){
      int rl = r0 + mt*16 + pq*8;
      int gm = bm + rl;
      float tot = ssb[0][rl] + ssb[1][rl] + ssb[2][rl] + ssb[3][rl];
      float sc = 1.f / fmaxf(sqrtf(tot), 1e-12f);
      #pragma unroll
      for (int nt = 0; nt < 8; nt++){
        int gn = bn + warpN*64 + nt*8 + 2*t4;
        float2 v;
        v.x = acc[mt][nt][pq*2]     * sc;
        v.y = acc[mt][nt][pq*2 + 1] * sc;
        *(float2*)(out + (size_t)gm*NOUT + gn) = v;
      }
    }
  }
}

// ---------------- launcher ----------------
extern "C" void kernel_launch(void* const* d_in, const int* in_sizes, int n_in,
                              void* d_out, int out_size)
{
  const int*   captions = (const int*)  d_in[1];
  const int*   lengths  = (const int*)  d_in[2];
  const float* emb      = (const float*)d_in[3];
  const float* w_ih_f   = (const float*)d_in[4];
  const float* w_hh_f   = (const float*)d_in[5];
  const float* b_ih_f   = (const float*)d_in[6];
  const float* b_hh_f   = (const float*)d_in[7];
  const float* w_ih_b   = (const float*)d_in[8];
  const float* w_hh_b   = (const float*)d_in[9];
  const float* b_ih_b   = (const float*)d_in[10];
  const float* b_hh_b   = (const float*)d_in[11];
  const float* w_out    = (const float*)d_in[12];
  const float* b_out    = (const float*)d_in[13];
  float* out = (float*)d_out;

  zero_state_kernel<<<(4*SB + 255)/256, 256>>>();
  setup_pairs_kernel<<<1, 256>>>();
  embed_kernel<<<BSZ*NSEQ, 256>>>(captions, lengths, emb);
  wcvt_kernel<<<(NOUT*2*HID + 255)/256, 256>>>(w_ih_f, w_ih_b, w_hh_f, w_hh_b, w_out);

  // input projections (single-pass fp16, both dirs)
  gemm16_bias<<<dim3(G4/128, (BSZ*NSEQ)/128, 2), 256>>>(b_ih_f, b_hh_f, b_ih_b, b_hh_b);

  // all 20 LSTM steps in one persistent kernel
  lstm_persist<<<LSTM_BLOCKS, 256>>>();

  // final projection + bias + fused per-group L2 normalize (cp.async pipeline)
  out_gemm_fused<<<dim3(NOUT/256, MROWS/64), 256>>>(b_out, out);
}

// round 15
// speedup vs baseline: 1.1521x; 1.0927x over previous
#include <cuda_runtime.h>
#include <cuda_fp16.h>
#include <stdint.h>

#define BSZ 32
#define NSEQ 20
#define DIM 512
#define HID 512
#define G4 2048          // 4*HID
#define NOUT 7680        // NT*SEM
#define SEM 256
#define NPAIR 190
#define MROWS (BSZ*NPAIR)   // 6080
#define SB (NSEQ*BSZ*HID)   // 640*512 per plane
#define FSZ (BSZ*NSEQ*NSEQ*HID)
#define LSTM_BLOCKS 176     // 16 col-tiles x 11 row-tiles

// ---------------- device scratch ----------------
__device__ __half g_WV16[BSZ*NSEQ*DIM];        // masked word vectors fp16
__device__ float g_X[2][BSZ*NSEQ*G4];          // input projections (f, b)
__device__ __half g_H16[2][2][SB];             // [dir][parity] hidden (fp16)
__device__ float g_C[2][SB];                   // cell state
__device__ __half g_WI16[2][G4*DIM];           // W_ih fp16 (f, b)
__device__ __half g_W16[2][G4*HID];            // W_hh fp16 (f, b)
__device__ float g_Ff[FSZ];                    // fp32 cumulative sums
__device__ float g_Fb[FSZ];
__device__ __half g_FF16[FSZ];                 // fp16 cumsum planes (out GEMM)
__device__ __half g_FB16[FSZ];
__device__ __half g_WO16[NOUT*2*HID];          // fp16 w_out
__device__ int   g_psF[NPAIR];
__device__ int   g_psB[NPAIR];
__device__ int   g_pcnt[NPAIR];
__device__ unsigned g_bar;

__device__ __forceinline__ float sigm(float x){ return 1.f/(1.f+__expf(-x)); }

__device__ __forceinline__ void mma16h(float c[4], const uint32_t a[4], const uint32_t b[2]){
  asm volatile("mma.sync.aligned.m16n8k16.row.col.f32.f16.f16.f32 "
      "{%0,%1,%2,%3}, {%4,%5,%6,%7}, {%8,%9}, {%0,%1,%2,%3};\n"
      : "+f"(c[0]), "+f"(c[1]), "+f"(c[2]), "+f"(c[3])
      : "r"(a[0]), "r"(a[1]), "r"(a[2]), "r"(a[3]), "r"(b[0]), "r"(b[1]));
}
__device__ __forceinline__ void ldsm4(uint32_t r[4], uint32_t saddr){
  asm volatile("ldmatrix.sync.aligned.m8n8.x4.shared.b16 {%0,%1,%2,%3}, [%4];"
      : "=r"(r[0]), "=r"(r[1]), "=r"(r[2]), "=r"(r[3]) : "r"(saddr));
}
__device__ __forceinline__ void cpa16(uint32_t dst, const void* src){
  asm volatile("cp.async.cg.shared.global [%0], [%1], 16;" :: "r"(dst), "l"(src) : "memory");
}
#define CPA_COMMIT() asm volatile("cp.async.commit_group;" ::: "memory")
#define CPA_WAIT1()  asm volatile("cp.async.wait_group 1;" ::: "memory")
#define CPA_WAIT0()  asm volatile("cp.async.wait_group 0;" ::: "memory")

// ---------------- small setup kernels ----------------
__global__ void zero_state_kernel(){
  int i = blockIdx.x*blockDim.x + threadIdx.x;
  if (i < 4*SB) (&g_H16[0][0][0])[i] = __float2half(0.f);
  if (i < 2*SB) (&g_C[0][0])[i] = 0.f;
}

__device__ __forceinline__ void st4h(__half* dst, float4 v){
  __half2 h0 = __floats2half2_rn(v.x, v.y);
  __half2 h1 = __floats2half2_rn(v.z, v.w);
  uint2 u;
  u.x = *(uint32_t*)&h0;
  u.y = *(uint32_t*)&h1;
  *(uint2*)dst = u;
}

// convert all weights to fp16 in ONE launch, vectorized x4
__global__ void wcvt_kernel(const float* __restrict__ wih_f, const float* __restrict__ wih_b,
                            const float* __restrict__ whh_f, const float* __restrict__ whh_b,
                            const float* __restrict__ wout){
  int i = (blockIdx.x*blockDim.x + threadIdx.x)*4;
  if (i < G4*HID){
    st4h(&g_WI16[0][i], *(const float4*)(wih_f + i));
    st4h(&g_WI16[1][i], *(const float4*)(wih_b + i));
    st4h(&g_W16[0][i],  *(const float4*)(whh_f + i));
    st4h(&g_W16[1][i],  *(const float4*)(whh_b + i));
  }
  if (i < NOUT*2*HID)
    st4h(&g_WO16[i], *(const float4*)(wout + i));
}

__global__ void setup_pairs_kernel(){
  if (threadIdx.x == 0) g_bar = 0;           // reset grid barrier each replay
  int p = threadIdx.x;
  if (p >= NPAIR) return;
  int cum = 0, k = 1, s = 0;
  for (int kk = 1; kk < NSEQ; kk++){
    int c = NSEQ - kk;
    if (p < cum + c){ k = kk; s = p - cum; break; }
    cum += c;
  }
  int e = s + k;
  g_psF[p] = s*NSEQ + e;
  g_psB[p] = e*NSEQ + s;
  g_pcnt[p] = k + 1;
}

__global__ void embed_kernel(const int* __restrict__ cap, const int* __restrict__ len,
                             const float* __restrict__ emb){
  int bt = blockIdx.x; int b = bt/NSEQ, t = bt%NSEQ;
  int tok = cap[bt];
  float m = (t < len[b]) ? 1.f : 0.f;
  const float* src = emb + (size_t)tok*DIM;
  for (int n = threadIdx.x; n < DIM; n += blockDim.x)
    g_WV16[bt*DIM + n] = __float2half(m * src[n]);
}

// =======================================================================
// FP16 projection GEMM: X[dir] = WV16 @ WI16[dir]^T + (b_ih + b_hh)
// =======================================================================
__global__ __launch_bounds__(256) void gemm16_bias(
    const float* __restrict__ bif, const float* __restrict__ bhf,
    const float* __restrict__ bib, const float* __restrict__ bhb)
{
  const int dir = blockIdx.z;
  const __half* __restrict__ A = g_WV16;
  const __half* __restrict__ B = g_WI16[dir];
  const float* __restrict__ b1 = dir ? bib : bif;
  const float* __restrict__ b2 = dir ? bhb : bhf;
  float* __restrict__ C = g_X[dir];

  __shared__ __align__(16) __half sA[128][40];
  __shared__ __align__(16) __half sB[128][40];
  const int tid = threadIdx.x, lane = tid & 31, wid = tid >> 5;
  const int warpM = wid >> 2, warpN = wid & 3;
  const int g = lane >> 2, t4 = lane & 3;
  const int bm = blockIdx.y*128, bn = blockIdx.x*128;

  const uint32_t sAu = (uint32_t)__cvta_generic_to_shared(&sA[0][0]);
  const uint32_t sBu = (uint32_t)__cvta_generic_to_shared(&sB[0][0]);
  const int bmat = lane >> 3;
  const uint32_t aOff = ((uint32_t)(warpM*64 + (lane & 15))*40 + (uint32_t)(lane >> 4)*8)*2;
  const uint32_t bOff = ((uint32_t)(warpN*32 + ((bmat >> 1)*8) + (lane & 7))*40
                        + (uint32_t)(bmat & 1)*8)*2;

  const int arow = tid >> 1, ak = (tid & 1)*16;
  uint4 ra[2], rb[2];
  {
    const __half* srcA = A + (size_t)(bm + arow)*DIM + ak;
    ra[0] = *(const uint4*)srcA;
    ra[1] = *(const uint4*)(srcA + 8);
    const __half* srcB = B + (size_t)(bn + arow)*DIM + ak;
    rb[0] = *(const uint4*)srcB;
    rb[1] = *(const uint4*)(srcB + 8);
  }

  float acc[4][4][4] = {};
  for (int k0 = 0; k0 < DIM; k0 += 32){
    __syncthreads();
    *(uint4*)&sA[arow][ak]     = ra[0];
    *(uint4*)&sA[arow][ak + 8] = ra[1];
    *(uint4*)&sB[arow][ak]     = rb[0];
    *(uint4*)&sB[arow][ak + 8] = rb[1];
    __syncthreads();
    if (k0 + 32 < DIM){
      const __half* srcA = A + (size_t)(bm + arow)*DIM + k0 + 32 + ak;
      ra[0] = *(const uint4*)srcA;
      ra[1] = *(const uint4*)(srcA + 8);
      const __half* srcB = B + (size_t)(bn + arow)*DIM + k0 + 32 + ak;
      rb[0] = *(const uint4*)srcB;
      rb[1] = *(const uint4*)(srcB + 8);
    }
    #pragma unroll
    for (int ks = 0; ks < 32; ks += 16){
      uint32_t a[4][4], bq[2][4];
      #pragma unroll
      for (int mt = 0; mt < 4; mt++)
        ldsm4(a[mt], sAu + aOff + (uint32_t)mt*16*80 + (uint32_t)ks*2);
      ldsm4(bq[0], sBu + bOff + (uint32_t)ks*2);
      ldsm4(bq[1], sBu + bOff + 16*80 + (uint32_t)ks*2);
      #pragma unroll
      for (int mt = 0; mt < 4; mt++)
        #pragma unroll
        for (int nt = 0; nt < 4; nt++)
          mma16h(acc[mt][nt], a[mt], &bq[nt>>1][(nt&1)*2]);
    }
  }
  #pragma unroll
  for (int mt = 0; mt < 4; mt++){
    int gm0 = bm + warpM*64 + mt*16 + g;
    #pragma unroll
    for (int nt = 0; nt < 4; nt++){
      int gn = bn + warpN*32 + nt*8 + 2*t4;
      float e0 = b1[gn] + b2[gn], e1 = b1[gn+1] + b2[gn+1];
      C[(size_t)gm0*G4 + gn]         = acc[mt][nt][0] + e0;
      C[(size_t)gm0*G4 + gn + 1]     = acc[mt][nt][1] + e1;
      C[(size_t)(gm0+8)*G4 + gn]     = acc[mt][nt][2] + e0;
      C[(size_t)(gm0+8)*G4 + gn + 1] = acc[mt][nt][3] + e1;
    }
  }
}

// =======================================================================
// Persistent LSTM: 176 blocks (16 col-tiles x 11 row-tiles), 2 blocks/SM.
// Each block: 64 rows x 32 hidden cols (x4 gates). 8 warps = 4M x 2N.
// =======================================================================
__device__ __forceinline__ void grid_sync(unsigned target){
  __syncthreads();
  if (threadIdx.x == 0){
    __threadfence();
    atomicAdd(&g_bar, 1u);
    while (atomicAdd(&g_bar, 0u) < target) {}
    __threadfence();
  }
  __syncthreads();
}

__global__ __launch_bounds__(256, 2) void lstm_persist()
{
  const int n0 = (blockIdx.x & 15) * 32;     // 32-col tile
  const int rt = blockIdx.x >> 4;            // 0..10
  const int tid = threadIdx.x, lane = tid & 31, wid = tid >> 5;
  const int warpM = wid & 3, warpN = wid >> 2;   // 4M x 2N
  const int g8 = lane >> 2, t4 = lane & 3;

  __shared__ __align__(16) uint16_t sA[64][24];    // 3072 B
  __shared__ __align__(16) uint16_t sB[128][24];   // 6144 B
  const uint32_t sAu = (uint32_t)__cvta_generic_to_shared(&sA[0][0]);
  const uint32_t sBu = (uint32_t)__cvta_generic_to_shared(&sB[0][0]);
  const int bmat = lane >> 3;
  const uint32_t aOff = ((uint32_t)(warpM*16 + (lane & 15))*24 + (uint32_t)(lane >> 4)*8)*2;
  const uint32_t bOff = ((uint32_t)(warpN*16 + ((bmat >> 1)*8) + (lane & 7))*24
                        + (uint32_t)(bmat & 1)*8)*2;
  const int arow = tid >> 1, ak8 = (tid & 1)*8;
  const int rbr = tid >> 1;                  // 0..127 B rows
  const int bk8 = (tid & 1)*8;

  for (int j = 0; j < NSEQ; j++){
    const int p = j & 1;
    const int tf = (j + 2) >> 1;             // ceil((j+1)/2) forward row tiles
    int dir, bm, rowLim;
    if (rt < tf){ dir = 0; bm = rt*64;                   rowLim = (j+1)*BSZ; }
    else        { dir = 1; bm = j*BSZ + (rt - tf)*64;    rowLim = NSEQ*BSZ; }

    const __half* __restrict__ Ain = g_H16[dir][p];
    const __half* __restrict__ W = g_W16[dir];
    const int gr = bm + arow;
    const bool aok = (gr < rowLim);
    const int wrow = (rbr >> 5)*HID + n0 + (rbr & 31);   // gate*512 + col

    float acc[4][2][4] = {};
    uint4 ra, rb;
    // prologue k=0
    if (tid < 128)
      ra = aok ? *(const uint4*)(Ain + (size_t)gr*HID + ak8) : make_uint4(0,0,0,0);
    rb = *(const uint4*)(W + (size_t)wrow*HID + bk8);

    for (int k0 = 0; k0 < HID; k0 += 16){
      __syncthreads();
      if (tid < 128) *(uint4*)&sA[arow][ak8] = ra;
      *(uint4*)&sB[rbr][bk8] = rb;
      __syncthreads();
      if (k0 + 16 < HID){
        int kn = k0 + 16;
        if (tid < 128)
          ra = aok ? *(const uint4*)(Ain + (size_t)gr*HID + kn + ak8) : make_uint4(0,0,0,0);
        rb = *(const uint4*)(W + (size_t)wrow*HID + kn + bk8);
      }
      uint32_t af[4];
      ldsm4(af, sAu + aOff);
      #pragma unroll
      for (int g = 0; g < 4; g++){
        uint32_t bq[4];
        ldsm4(bq, sBu + (uint32_t)g*32*48 + bOff);
        mma16h(acc[g][0], af, &bq[0]);
        mma16h(acc[g][1], af, &bq[2]);
      }
    }

    // ---- epilogue: gates -> c,h -> state + cumulative F (32 cols/block) ----
    {
      const float* __restrict__ X = g_X[dir];
      float* __restrict__ C = g_C[dir];
      __half* __restrict__ Hn = g_H16[dir][p^1];
      float* __restrict__ F  = dir ? g_Fb  : g_Ff;
      __half* __restrict__ F16 = dir ? g_FB16 : g_FF16;

      #pragma unroll
      for (int rr = 0; rr < 2; rr++){
        int gm = bm + warpM*16 + g8 + rr*8;
        if (gm >= rowLim) continue;
        int chain = gm >> 5, b = gm & 31;
        int t = dir ? (chain - j) : j;
        size_t xrow = (size_t)(b*NSEQ + t)*G4;
        size_t fbase;
        bool first;
        if (dir == 0){ fbase = ((size_t)(b*NSEQ + chain)*NSEQ + j)*HID; first = (j == chain); }
        else         { fbase = ((size_t)(b*NSEQ + chain)*NSEQ + t)*HID; first = (t == chain); }
        #pragma unroll
        for (int nt = 0; nt < 2; nt++){
          #pragma unroll
          for (int cc = 0; cc < 2; cc++){
            int n = n0 + warpN*16 + nt*8 + t4*2 + cc;
            int ai = rr*2 + cc;
            float gi = acc[0][nt][ai] + X[xrow + n];
            float gf = acc[1][nt][ai] + X[xrow + 512 + n];
            float gc = acc[2][nt][ai] + X[xrow + 1024 + n];
            float go = acc[3][nt][ai] + X[xrow + 1536 + n];
            size_t si = (size_t)gm*HID + n;
            float c = sigm(gf)*C[si] + sigm(gi)*tanhf(gc);
            float h = sigm(go)*tanhf(c);
            C[si] = c;
            Hn[si] = __float2half(h);
            float prev = first ? 0.f : F[fbase + n + (dir ? (int)HID : -(int)HID)];
            float v = prev + h;
            F[fbase + n]   = v;
            F16[fbase + n] = __float2half(v);
          }
        }
      }
    }
    grid_sync((unsigned)(LSTM_BLOCKS*(j+1)));
  }
}

// =======================================================================
// out GEMM + fused L2 normalize: cp.async 3-stage pipeline (R14, unchanged).
// BM=64, BN=256, 256 threads = 8 warps (2M x 4N). grid (30, 95).
// =======================================================================
#define OGA 5120u      // A stage stride: 64*40*2
#define OGB 20480u     // B stage stride: 256*40*2

__global__ __launch_bounds__(256) void out_gemm_fused(const float* __restrict__ bout,
                                                      float* __restrict__ out)
{
  __shared__ __align__(16) __half sA[3][64][40];
  __shared__ __align__(16) __half sB[3][256][40];
  __shared__ int offF[64], offB[64], cnt[64];
  __shared__ float ssb[4][64];
  const int tid = threadIdx.x, lane = tid & 31, wid = tid >> 5;
  const int warpM = wid >> 2, warpN = wid & 3;
  const int g = lane >> 2, t4 = lane & 3;
  const int bm = blockIdx.y*64, bn = blockIdx.x*256;

  if (tid < 64){
    int gm = bm + tid;
    int b = gm / NPAIR, p = gm % NPAIR;
    offF[tid] = (b*NSEQ*NSEQ + g_psF[p])*HID;
    offB[tid] = (b*NSEQ*NSEQ + g_psB[p])*HID;
    cnt[tid]  = g_pcnt[p];
  }
  __syncthreads();

  const uint32_t sAu = (uint32_t)__cvta_generic_to_shared(&sA[0][0][0]);
  const uint32_t sBu = (uint32_t)__cvta_generic_to_shared(&sB[0][0][0]);
  const int bmat = lane >> 3;
  const uint32_t aOff = ((uint32_t)(warpM*32 + (lane & 15))*40 + (uint32_t)(lane >> 4)*8)*2;
  const uint32_t bOff = ((uint32_t)(warpN*64 + ((bmat >> 1)*8) + (lane & 7))*40
                        + (uint32_t)(bmat & 1)*8)*2;

  const int arow = tid >> 2, ak = (tid & 3)*8;
  const int aF = offF[arow], aB = offB[arow];
  const uint32_t aDst = sAu + ((uint32_t)arow*40 + (uint32_t)ak)*2;
  uint32_t bDst[4];
  const __half* bSrc[4];
  #pragma unroll
  for (int s = 0; s < 4; s++){
    int idx = tid + s*256;
    int br = idx >> 2, bk = (idx & 3)*8;
    bDst[s] = sBu + ((uint32_t)br*40 + (uint32_t)bk)*2;
    bSrc[s] = g_WO16 + (size_t)(bn + br)*(2*HID) + bk;
  }

  #define OG_ISSUE(stg, it) do{                                               \
    int k_ = (it)*32 + ak;                                                    \
    const __half* srcA_ = (k_ < HID) ? (g_FF16 + aF + k_)                     \
                                     : (g_FB16 + aB + k_ - HID);              \
    cpa16(aDst + (uint32_t)(stg)*OGA, srcA_);                                 \
    _Pragma("unroll")                                                         \
    for (int s_ = 0; s_ < 4; s_++)                                            \
      cpa16(bDst[s_] + (uint32_t)(stg)*OGB, bSrc[s_] + (it)*32);              \
    CPA_COMMIT();                                                             \
  } while(0)

  OG_ISSUE(0, 0);
  OG_ISSUE(1, 1);

  float acc[2][8][4] = {};
  int stg = 0;
  for (int it = 0; it < 32; it++){
    if (it >= 30) CPA_WAIT0(); else CPA_WAIT1();
    __syncthreads();
    if (it + 2 < 32){
      int ns = stg + 2; if (ns >= 3) ns -= 3;
      OG_ISSUE(ns, it + 2);
    }
    #pragma unroll
    for (int ks = 0; ks < 32; ks += 16){
      uint32_t a[2][4];
      ldsm4(a[0], sAu + (uint32_t)stg*OGA + aOff + (uint32_t)ks*2);
      ldsm4(a[1], sAu + (uint32_t)stg*OGA + aOff + 16*80 + (uint32_t)ks*2);
      #pragma unroll
      for (int q = 0; q < 4; q++){
        uint32_t bq[4];
        ldsm4(bq, sBu + (uint32_t)stg*OGB + bOff + (uint32_t)q*16*80 + (uint32_t)ks*2);
        #pragma unroll
        for (int mt = 0; mt < 2; mt++){
          mma16h(acc[mt][q*2],     a[mt], &bq[0]);
          mma16h(acc[mt][q*2 + 1], a[mt], &bq[2]);
        }
      }
    }
    if (++stg >= 3) stg = 0;
  }

  // ---- epilogue: + cnt*bias, fused L2-normalize over the 256-wide group ----
  const int r0 = warpM*32 + g;
  float ssr[2][2] = {};
  #pragma unroll
  for (int mt = 0; mt < 2; mt++){
    int rl = r0 + mt*16;
    float c0 = (float)cnt[rl], c1 = (float)cnt[rl + 8];
    #pragma unroll
    for (int nt = 0; nt < 8; nt++){
      int gn = bn + warpN*64 + nt*8 + 2*t4;
      float b0 = bout[gn], b1 = bout[gn + 1];
      acc[mt][nt][0] += c0*b0;  acc[mt][nt][1] += c0*b1;
      acc[mt][nt][2] += c1*b0;  acc[mt][nt][3] += c1*b1;
      ssr[mt][0] += acc[mt][nt][0]*acc[mt][nt][0] + acc[mt][nt][1]*acc[mt][nt][1];
      ssr[mt][1] += acc[mt][nt][2]*acc[mt][nt][2] + acc[mt][nt][3]*acc[mt][nt][3];
    }
  }
  #pragma unroll
  for (int mt = 0; mt < 2; mt++)
    #pragma unroll
    for (int pq = 0; pq < 2; pq++){
      ssr[mt][pq] += __shfl_xor_sync(0xffffffffu, ssr[mt][pq], 1);
      ssr[mt][pq] += __shfl_xor_sync(0xffffffffu, ssr[mt][pq], 2);
    }
  __syncthreads();
  if (t4 == 0){
    ssb[warpN][r0]      = ssr[0][0];
    ssb[warpN][r0 + 8]  = ssr[0][1];
    ssb[warpN][r0 + 16] = ssr[1][0];
    ssb[warpN][r0 + 24] = ssr[1][1];
  }
  __syncthreads();
  #pragma unroll
  for (int mt = 0; mt < 2; mt++){
    #pragma unroll
    for (int pq = 0; pq < 2; pq++){
      int rl = r0 + mt*16 + pq*8;
      int gm = bm + rl;
      float tot = ssb[0][rl] + ssb[1][rl] + ssb[2][rl] + ssb[3][rl];
      float sc = 1.f / fmaxf(sqrtf(tot), 1e-12f);
      #pragma unroll
      for (int nt = 0; nt < 8; nt++){
        int gn = bn + warpN*64 + nt*8 + 2*t4;
        float2 v;
        v.x = acc[mt][nt][pq*2]     * sc;
        v.y = acc[mt][nt][pq*2 + 1] * sc;
        *(float2*)(out + (size_t)gm*NOUT + gn) = v;
      }
    }
  }
}

// ---------------- launcher ----------------
extern "C" void kernel_launch(void* const* d_in, const int* in_sizes, int n_in,
                              void* d_out, int out_size)
{
  const int*   captions = (const int*)  d_in[1];
  const int*   lengths  = (const int*)  d_in[2];
  const float* emb      = (const float*)d_in[3];
  const float* w_ih_f   = (const float*)d_in[4];
  const float* w_hh_f   = (const float*)d_in[5];
  const float* b_ih_f   = (const float*)d_in[6];
  const float* b_hh_f   = (const float*)d_in[7];
  const float* w_ih_b   = (const float*)d_in[8];
  const float* w_hh_b   = (const float*)d_in[9];
  const float* b_ih_b   = (const float*)d_in[10];
  const float* b_hh_b   = (const float*)d_in[11];
  const float* w_out    = (const float*)d_in[12];
  const float* b_out    = (const float*)d_in[13];
  float* out = (float*)d_out;

  zero_state_kernel<<<(4*SB + 255)/256, 256>>>();
  setup_pairs_kernel<<<1, 256>>>();
  embed_kernel<<<BSZ*NSEQ, 256>>>(captions, lengths, emb);
  wcvt_kernel<<<(NOUT*2*HID/4 + 255)/256, 256>>>(w_ih_f, w_ih_b, w_hh_f, w_hh_b, w_out);

  // input projections (single-pass fp16, both dirs)
  gemm16_bias<<<dim3(G4/128, (BSZ*NSEQ)/128, 2), 256>>>(b_ih_f, b_hh_f, b_ih_b, b_hh_b);

  // all 20 LSTM steps in one persistent kernel (176 blocks, 2/SM guaranteed)
  lstm_persist<<<LSTM_BLOCKS, 256>>>();

  // final projection + bias + fused per-group L2 normalize (cp.async pipeline)
  out_gemm_fused<<<dim3(NOUT/256, MROWS/64), 256>>>(b_out, out);
}

// round 16
// speedup vs baseline: 1.1608x; 1.0076x over previous
#include <cuda_runtime.h>
#include <cuda_fp16.h>
#include <stdint.h>

#define BSZ 32
#define NSEQ 20
#define DIM 512
#define HID 512
#define G4 2048          // 4*HID
#define NOUT 7680        // NT*SEM
#define SEM 256
#define NPAIR 190
#define MROWS (BSZ*NPAIR)   // 6080
#define SB (NSEQ*BSZ*HID)   // 640*512 per plane
#define FSZ (BSZ*NSEQ*NSEQ*HID)
#define LSTM_BLOCKS 176     // 16 col-tiles x 11 row-tiles
#define NW (G4*HID)         // 1048576
#define NWO (NOUT*2*HID)    // 7864320

// ---------------- device scratch ----------------
__device__ __half g_WV16[BSZ*NSEQ*DIM];        // masked word vectors fp16
__device__ float g_X[2][BSZ*NSEQ*G4];          // input projections (f, b)
__device__ __half g_H16[2][2][SB];             // [dir][parity] hidden (fp16)
__device__ float g_C[2][SB];                   // cell state
__device__ __half g_WI16[2][G4*DIM];           // W_ih fp16 (f, b)
__device__ __half g_W16[2][G4*HID];            // W_hh fp16 (f, b)
__device__ float g_Ff[FSZ];                    // fp32 cumulative sums
__device__ float g_Fb[FSZ];
__device__ __half g_FF16[FSZ];                 // fp16 cumsum planes (out GEMM)
__device__ __half g_FB16[FSZ];
__device__ __half g_WO16[NOUT*2*HID];          // fp16 w_out
__device__ int   g_psF[NPAIR];
__device__ int   g_psB[NPAIR];
__device__ int   g_pcnt[NPAIR];
__device__ unsigned g_bar;

__device__ __forceinline__ float sigm(float x){ return 1.f/(1.f+__expf(-x)); }

__device__ __forceinline__ void mma16h(float c[4], const uint32_t a[4], const uint32_t b[2]){
  asm volatile("mma.sync.aligned.m16n8k16.row.col.f32.f16.f16.f32 "
      "{%0,%1,%2,%3}, {%4,%5,%6,%7}, {%8,%9}, {%0,%1,%2,%3};\n"
      : "+f"(c[0]), "+f"(c[1]), "+f"(c[2]), "+f"(c[3])
      : "r"(a[0]), "r"(a[1]), "r"(a[2]), "r"(a[3]), "r"(b[0]), "r"(b[1]));
}
__device__ __forceinline__ void ldsm4(uint32_t r[4], uint32_t saddr){
  asm volatile("ldmatrix.sync.aligned.m8n8.x4.shared.b16 {%0,%1,%2,%3}, [%4];"
      : "=r"(r[0]), "=r"(r[1]), "=r"(r[2]), "=r"(r[3]) : "r"(saddr));
}
__device__ __forceinline__ void cpa16(uint32_t dst, const void* src){
  asm volatile("cp.async.cg.shared.global [%0], [%1], 16;" :: "r"(dst), "l"(src) : "memory");
}
#define CPA_COMMIT() asm volatile("cp.async.commit_group;" ::: "memory")
#define CPA_WAIT1()  asm volatile("cp.async.wait_group 1;" ::: "memory")
#define CPA_WAIT0()  asm volatile("cp.async.wait_group 0;" ::: "memory")

__device__ __forceinline__ void st4h(__half* dst, float4 v){
  __half2 h0 = __floats2half2_rn(v.x, v.y);
  __half2 h1 = __floats2half2_rn(v.z, v.w);
  uint2 u;
  u.x = *(uint32_t*)&h0;
  u.y = *(uint32_t*)&h1;
  *(uint2*)dst = u;
}

// =======================================================================
// ONE init kernel: zero state, pairs+barrier, embed, all weight converts.
// grid = NWO/4/256 = 7680 blocks; each thread owns 4 consecutive elements
// of every range.
// =======================================================================
__global__ void init_kernel(const int* __restrict__ cap, const int* __restrict__ len,
                            const float* __restrict__ emb,
                            const float* __restrict__ wih_f, const float* __restrict__ wih_b,
                            const float* __restrict__ whh_f, const float* __restrict__ whh_b,
                            const float* __restrict__ wout)
{
  int e = (blockIdx.x*blockDim.x + threadIdx.x)*4;
  if (e < NWO)
    st4h(&g_WO16[e], *(const float4*)(wout + e));
  if (e < NW){
    st4h(&g_WI16[0][e], *(const float4*)(wih_f + e));
    st4h(&g_WI16[1][e], *(const float4*)(wih_b + e));
    st4h(&g_W16[0][e],  *(const float4*)(whh_f + e));
    st4h(&g_W16[1][e],  *(const float4*)(whh_b + e));
  }
  if (e < 4*SB)
    *(uint2*)(&g_H16[0][0][0] + e) = make_uint2(0u, 0u);
  if (e < 2*SB)
    *(float4*)(&g_C[0][0] + e) = make_float4(0.f, 0.f, 0.f, 0.f);
  if (e < BSZ*NSEQ*DIM){
    int bt = e / DIM, col = e % DIM;
    int b = bt / NSEQ, t = bt % NSEQ;
    float m = (t < len[b]) ? 1.f : 0.f;
    float4 v = *(const float4*)(emb + (size_t)cap[bt]*DIM + col);
    v.x *= m; v.y *= m; v.z *= m; v.w *= m;
    st4h(&g_WV16[e], v);
  }
  if (blockIdx.x == 0){
    if (threadIdx.x == 0) g_bar = 0;
    int p = threadIdx.x;
    if (p < NPAIR){
      int cum = 0, k = 1, s = 0;
      for (int kk = 1; kk < NSEQ; kk++){
        int c = NSEQ - kk;
        if (p < cum + c){ k = kk; s = p - cum; break; }
        cum += c;
      }
      int ee = s + k;
      g_psF[p] = s*NSEQ + ee;
      g_psB[p] = ee*NSEQ + s;
      g_pcnt[p] = k + 1;
    }
  }
}

// =======================================================================
// FP16 projection GEMM: X[dir] = WV16 @ WI16[dir]^T + (b_ih + b_hh)
// =======================================================================
__global__ __launch_bounds__(256) void gemm16_bias(
    const float* __restrict__ bif, const float* __restrict__ bhf,
    const float* __restrict__ bib, const float* __restrict__ bhb)
{
  const int dir = blockIdx.z;
  const __half* __restrict__ A = g_WV16;
  const __half* __restrict__ B = g_WI16[dir];
  const float* __restrict__ b1 = dir ? bib : bif;
  const float* __restrict__ b2 = dir ? bhb : bhf;
  float* __restrict__ C = g_X[dir];

  __shared__ __align__(16) __half sA[128][40];
  __shared__ __align__(16) __half sB[128][40];
  const int tid = threadIdx.x, lane = tid & 31, wid = tid >> 5;
  const int warpM = wid >> 2, warpN = wid & 3;
  const int g = lane >> 2, t4 = lane & 3;
  const int bm = blockIdx.y*128, bn = blockIdx.x*128;

  const uint32_t sAu = (uint32_t)__cvta_generic_to_shared(&sA[0][0]);
  const uint32_t sBu = (uint32_t)__cvta_generic_to_shared(&sB[0][0]);
  const int bmat = lane >> 3;
  const uint32_t aOff = ((uint32_t)(warpM*64 + (lane & 15))*40 + (uint32_t)(lane >> 4)*8)*2;
  const uint32_t bOff = ((uint32_t)(warpN*32 + ((bmat >> 1)*8) + (lane & 7))*40
                        + (uint32_t)(bmat & 1)*8)*2;

  const int arow = tid >> 1, ak = (tid & 1)*16;
  uint4 ra[2], rb[2];
  {
    const __half* srcA = A + (size_t)(bm + arow)*DIM + ak;
    ra[0] = *(const uint4*)srcA;
    ra[1] = *(const uint4*)(srcA + 8);
    const __half* srcB = B + (size_t)(bn + arow)*DIM + ak;
    rb[0] = *(const uint4*)srcB;
    rb[1] = *(const uint4*)(srcB + 8);
  }

  float acc[4][4][4] = {};
  for (int k0 = 0; k0 < DIM; k0 += 32){
    __syncthreads();
    *(uint4*)&sA[arow][ak]     = ra[0];
    *(uint4*)&sA[arow][ak + 8] = ra[1];
    *(uint4*)&sB[arow][ak]     = rb[0];
    *(uint4*)&sB[arow][ak + 8] = rb[1];
    __syncthreads();
    if (k0 + 32 < DIM){
      const __half* srcA = A + (size_t)(bm + arow)*DIM + k0 + 32 + ak;
      ra[0] = *(const uint4*)srcA;
      ra[1] = *(const uint4*)(srcA + 8);
      const __half* srcB = B + (size_t)(bn + arow)*DIM + k0 + 32 + ak;
      rb[0] = *(const uint4*)srcB;
      rb[1] = *(const uint4*)(srcB + 8);
    }
    #pragma unroll
    for (int ks = 0; ks < 32; ks += 16){
      uint32_t a[4][4], bq[2][4];
      #pragma unroll
      for (int mt = 0; mt < 4; mt++)
        ldsm4(a[mt], sAu + aOff + (uint32_t)mt*16*80 + (uint32_t)ks*2);
      ldsm4(bq[0], sBu + bOff + (uint32_t)ks*2);
      ldsm4(bq[1], sBu + bOff + 16*80 + (uint32_t)ks*2);
      #pragma unroll
      for (int mt = 0; mt < 4; mt++)
        #pragma unroll
        for (int nt = 0; nt < 4; nt++)
          mma16h(acc[mt][nt], a[mt], &bq[nt>>1][(nt&1)*2]);
    }
  }
  #pragma unroll
  for (int mt = 0; mt < 4; mt++){
    int gm0 = bm + warpM*64 + mt*16 + g;
    #pragma unroll
    for (int nt = 0; nt < 4; nt++){
      int gn = bn + warpN*32 + nt*8 + 2*t4;
      float e0 = b1[gn] + b2[gn], e1 = b1[gn+1] + b2[gn+1];
      C[(size_t)gm0*G4 + gn]         = acc[mt][nt][0] + e0;
      C[(size_t)gm0*G4 + gn + 1]     = acc[mt][nt][1] + e1;
      C[(size_t)(gm0+8)*G4 + gn]     = acc[mt][nt][2] + e0;
      C[(size_t)(gm0+8)*G4 + gn + 1] = acc[mt][nt][3] + e1;
    }
  }
}

// =======================================================================
// Persistent LSTM: 176 blocks (16 col-tiles x 11 row-tiles), 2 blocks/SM.
// =======================================================================
__device__ __forceinline__ void grid_sync(unsigned target){
  __syncthreads();
  if (threadIdx.x == 0){
    __threadfence();
    atomicAdd(&g_bar, 1u);
    while (atomicAdd(&g_bar, 0u) < target) {}
    __threadfence();
  }
  __syncthreads();
}

__global__ __launch_bounds__(256, 2) void lstm_persist()
{
  const int n0 = (blockIdx.x & 15) * 32;     // 32-col tile
  const int rt = blockIdx.x >> 4;            // 0..10
  const int tid = threadIdx.x, lane = tid & 31, wid = tid >> 5;
  const int warpM = wid & 3, warpN = wid >> 2;   // 4M x 2N
  const int g8 = lane >> 2, t4 = lane & 3;

  __shared__ __align__(16) uint16_t sA[64][24];    // 3072 B
  __shared__ __align__(16) uint16_t sB[128][24];   // 6144 B
  const uint32_t sAu = (uint32_t)__cvta_generic_to_shared(&sA[0][0]);
  const uint32_t sBu = (uint32_t)__cvta_generic_to_shared(&sB[0][0]);
  const int bmat = lane >> 3;
  const uint32_t aOff = ((uint32_t)(warpM*16 + (lane & 15))*24 + (uint32_t)(lane >> 4)*8)*2;
  const uint32_t bOff = ((uint32_t)(warpN*16 + ((bmat >> 1)*8) + (lane & 7))*24
                        + (uint32_t)(bmat & 1)*8)*2;
  const int arow = tid >> 1, ak8 = (tid & 1)*8;
  const int rbr = tid >> 1;                  // 0..127 B rows
  const int bk8 = (tid & 1)*8;

  for (int j = 0; j < NSEQ; j++){
    const int p = j & 1;
    const int tf = (j + 2) >> 1;             // ceil((j+1)/2) forward row tiles
    int dir, bm, rowLim;
    if (rt < tf){ dir = 0; bm = rt*64;                   rowLim = (j+1)*BSZ; }
    else        { dir = 1; bm = j*BSZ + (rt - tf)*64;    rowLim = NSEQ*BSZ; }

    const __half* __restrict__ Ain = g_H16[dir][p];
    const __half* __restrict__ W = g_W16[dir];
    const int gr = bm + arow;
    const bool aok = (gr < rowLim);
    const int wrow = (rbr >> 5)*HID + n0 + (rbr & 31);   // gate*512 + col

    float acc[4][2][4] = {};
    uint4 ra, rb;
    if (tid < 128)
      ra = aok ? *(const uint4*)(Ain + (size_t)gr*HID + ak8) : make_uint4(0,0,0,0);
    rb = *(const uint4*)(W + (size_t)wrow*HID + bk8);

    for (int k0 = 0; k0 < HID; k0 += 16){
      __syncthreads();
      if (tid < 128) *(uint4*)&sA[arow][ak8] = ra;
      *(uint4*)&sB[rbr][bk8] = rb;
      __syncthreads();
      if (k0 + 16 < HID){
        int kn = k0 + 16;
        if (tid < 128)
          ra = aok ? *(const uint4*)(Ain + (size_t)gr*HID + kn + ak8) : make_uint4(0,0,0,0);
        rb = *(const uint4*)(W + (size_t)wrow*HID + kn + bk8);
      }
      uint32_t af[4];
      ldsm4(af, sAu + aOff);
      #pragma unroll
      for (int g = 0; g < 4; g++){
        uint32_t bq[4];
        ldsm4(bq, sBu + (uint32_t)g*32*48 + bOff);
        mma16h(acc[g][0], af, &bq[0]);
        mma16h(acc[g][1], af, &bq[2]);
      }
    }

    // ---- epilogue: gates -> c,h -> state + cumulative F (32 cols/block) ----
    {
      const float* __restrict__ X = g_X[dir];
      float* __restrict__ C = g_C[dir];
      __half* __restrict__ Hn = g_H16[dir][p^1];
      float* __restrict__ F  = dir ? g_Fb  : g_Ff;
      __half* __restrict__ F16 = dir ? g_FB16 : g_FF16;

      #pragma unroll
      for (int rr = 0; rr < 2; rr++){
        int gm = bm + warpM*16 + g8 + rr*8;
        if (gm >= rowLim) continue;
        int chain = gm >> 5, b = gm & 31;
        int t = dir ? (chain - j) : j;
        size_t xrow = (size_t)(b*NSEQ + t)*G4;
        size_t fbase;
        bool first;
        if (dir == 0){ fbase = ((size_t)(b*NSEQ + chain)*NSEQ + j)*HID; first = (j == chain); }
        else         { fbase = ((size_t)(b*NSEQ + chain)*NSEQ + t)*HID; first = (t == chain); }
        #pragma unroll
        for (int nt = 0; nt < 2; nt++){
          #pragma unroll
          for (int cc = 0; cc < 2; cc++){
            int n = n0 + warpN*16 + nt*8 + t4*2 + cc;
            int ai = rr*2 + cc;
            float gi = acc[0][nt][ai] + X[xrow + n];
            float gf = acc[1][nt][ai] + X[xrow + 512 + n];
            float gc = acc[2][nt][ai] + X[xrow + 1024 + n];
            float go = acc[3][nt][ai] + X[xrow + 1536 + n];
            size_t si = (size_t)gm*HID + n;
            float c = sigm(gf)*C[si] + sigm(gi)*tanhf(gc);
            float h = sigm(go)*tanhf(c);
            C[si] = c;
            Hn[si] = __float2half(h);
            float prev = first ? 0.f : F[fbase + n + (dir ? (int)HID : -(int)HID)];
            float v = prev + h;
            F[fbase + n]   = v;
            F16[fbase + n] = __float2half(v);
          }
        }
      }
    }
    grid_sync((unsigned)(LSTM_BLOCKS*(j+1)));
  }
}

// =======================================================================
// out GEMM + fused L2 normalize: cp.async 3-stage pipeline.
// BM=128, BN=256 (= one SEM group), 512 threads = 16 warps (4M x 4N),
// warp tile 32x64. No register prefetch state (cp.async) -> no spill.
// grid (30, 48).
// =======================================================================
#define OGA 10240u     // A stage stride: 128*40*2
#define OGB 20480u     // B stage stride: 256*40*2

__global__ __launch_bounds__(512) void out_gemm_fused(const float* __restrict__ bout,
                                                      float* __restrict__ out)
{
  __shared__ __align__(16) __half sA[3][128][40];
  __shared__ __align__(16) __half sB[3][256][40];
  __shared__ int offF[128], offB[128], cnt[128];
  __shared__ float ssb[4][128];
  const int tid = threadIdx.x, lane = tid & 31, wid = tid >> 5;
  const int warpM = wid >> 2, warpN = wid & 3;
  const int g = lane >> 2, t4 = lane & 3;
  const int bm = blockIdx.y*128, bn = blockIdx.x*256;

  if (tid < 128){
    int gm = bm + tid;
    if (gm < MROWS){
      int b = gm / NPAIR, p = gm % NPAIR;
      offF[tid] = (b*NSEQ*NSEQ + g_psF[p])*HID;
      offB[tid] = (b*NSEQ*NSEQ + g_psB[p])*HID;
      cnt[tid]  = g_pcnt[p];
    } else { offF[tid] = 0; offB[tid] = 0; cnt[tid] = 0; }
  }
  __syncthreads();

  const uint32_t sAu = (uint32_t)__cvta_generic_to_shared(&sA[0][0][0]);
  const uint32_t sBu = (uint32_t)__cvta_generic_to_shared(&sB[0][0][0]);
  const int bmat = lane >> 3;
  const uint32_t aOff = ((uint32_t)(warpM*32 + (lane & 15))*40 + (uint32_t)(lane >> 4)*8)*2;
  const uint32_t bOff = ((uint32_t)(warpN*64 + ((bmat >> 1)*8) + (lane & 7))*40
                        + (uint32_t)(bmat & 1)*8)*2;

  // loaders: A 128x32 halves -> 1 x 16B/thread; B 256x32 -> 2 x 16B/thread
  const int arow = tid >> 2, ak = (tid & 3)*8;
  const int aF = offF[arow], aB = offB[arow];
  const uint32_t aDst = sAu + ((uint32_t)arow*40 + (uint32_t)ak)*2;
  uint32_t bDst[2];
  const __half* bSrc[2];
  #pragma unroll
  for (int s = 0; s < 2; s++){
    int idx = tid + s*512;
    int br = idx >> 2, bk = (idx & 3)*8;
    bDst[s] = sBu + ((uint32_t)br*40 + (uint32_t)bk)*2;
    bSrc[s] = g_WO16 + (size_t)(bn + br)*(2*HID) + bk;
  }

  #define OG_ISSUE(stg, it) do{                                               \
    int k_ = (it)*32 + ak;                                                    \
    const __half* srcA_ = (k_ < HID) ? (g_FF16 + aF + k_)                     \
                                     : (g_FB16 + aB + k_ - HID);              \
    cpa16(aDst + (uint32_t)(stg)*OGA, srcA_);                                 \
    _Pragma("unroll")                                                         \
    for (int s_ = 0; s_ < 2; s_++)                                            \
      cpa16(bDst[s_] + (uint32_t)(stg)*OGB, bSrc[s_] + (it)*32);              \
    CPA_COMMIT();                                                             \
  } while(0)

  OG_ISSUE(0, 0);
  OG_ISSUE(1, 1);

  float acc[2][8][4] = {};
  int stg = 0;
  for (int it = 0; it < 32; it++){
    if (it >= 30) CPA_WAIT0(); else CPA_WAIT1();
    __syncthreads();
    if (it + 2 < 32){
      int ns = stg + 2; if (ns >= 3) ns -= 3;
      OG_ISSUE(ns, it + 2);
    }
    #pragma unroll
    for (int ks = 0; ks < 32; ks += 16){
      uint32_t a[2][4];
      ldsm4(a[0], sAu + (uint32_t)stg*OGA + aOff + (uint32_t)ks*2);
      ldsm4(a[1], sAu + (uint32_t)stg*OGA + aOff + 16*80 + (uint32_t)ks*2);
      #pragma unroll
      for (int q = 0; q < 4; q++){
        uint32_t bq[4];
        ldsm4(bq, sBu + (uint32_t)stg*OGB + bOff + (uint32_t)q*16*80 + (uint32_t)ks*2);
        #pragma unroll
        for (int mt = 0; mt < 2; mt++){
          mma16h(acc[mt][q*2],     a[mt], &bq[0]);
          mma16h(acc[mt][q*2 + 1], a[mt], &bq[2]);
        }
      }
    }
    if (++stg >= 3) stg = 0;
  }

  // ---- epilogue: + cnt*bias, fused L2-normalize over the 256-wide group ----
  const int r0 = warpM*32 + g;        // local rows r0/+8 (mt=0), +16/+24 (mt=1)
  float ssr[2][2] = {};
  #pragma unroll
  for (int mt = 0; mt < 2; mt++){
    int rl = r0 + mt*16;
    float c0 = (float)cnt[rl], c1 = (float)cnt[rl + 8];
    #pragma unroll
    for (int nt = 0; nt < 8; nt++){
      int gn = bn + warpN*64 + nt*8 + 2*t4;
      float b0 = bout[gn], b1 = bout[gn + 1];
      acc[mt][nt][0] += c0*b0;  acc[mt][nt][1] += c0*b1;
      acc[mt][nt][2] += c1*b0;  acc[mt][nt][3] += c1*b1;
      ssr[mt][0] += acc[mt][nt][0]*acc[mt][nt][0] + acc[mt][nt][1]*acc[mt][nt][1];
      ssr[mt][1] += acc[mt][nt][2]*acc[mt][nt][2] + acc[mt][nt][3]*acc[mt][nt][3];
    }
  }
  #pragma unroll
  for (int mt = 0; mt < 2; mt++)
    #pragma unroll
    for (int pq = 0; pq < 2; pq++){
      ssr[mt][pq] += __shfl_xor_sync(0xffffffffu, ssr[mt][pq], 1);
      ssr[mt][pq] += __shfl_xor_sync(0xffffffffu, ssr[mt][pq], 2);
    }
  __syncthreads();
  if (t4 == 0){
    ssb[warpN][r0]      = ssr[0][0];
    ssb[warpN][r0 + 8]  = ssr[0][1];
    ssb[warpN][r0 + 16] = ssr[1][0];
    ssb[warpN][r0 + 24] = ssr[1][1];
  }
  __syncthreads();
  #pragma unroll
  for (int mt = 0; mt < 2; mt++){
    #pragma unroll
    for (int pq = 0; pq < 2; pq++){
      int rl = r0 + mt*16 + pq*8;
      int gm = bm + rl;
      float tot = ssb[0][rl] + ssb[1][rl] + ssb[2][rl] + ssb[3][rl];
      float sc = 1.f / fmaxf(sqrtf(tot), 1e-12f);
      if (gm < MROWS){
        #pragma unroll
        for (int nt = 0; nt < 8; nt++){
          int gn = bn + warpN*64 + nt*8 + 2*t4;
          float2 v;
          v.x = acc[mt][nt][pq*2]     * sc;
          v.y = acc[mt][nt][pq*2 + 1] * sc;
          *(float2*)(out + (size_t)gm*NOUT + gn) = v;
        }
      }
    }
  }
}

// ---------------- launcher ----------------
extern "C" void kernel_launch(void* const* d_in, const int* in_sizes, int n_in,
                              void* d_out, int out_size)
{
  const int*   captions = (const int*)  d_in[1];
  const int*   lengths  = (const int*)  d_in[2];
  const float* emb      = (const float*)d_in[3];
  const float* w_ih_f   = (const float*)d_in[4];
  const float* w_hh_f   = (const float*)d_in[5];
  const float* b_ih_f   = (const float*)d_in[6];
  const float* b_hh_f   = (const float*)d_in[7];
  const float* w_ih_b   = (const float*)d_in[8];
  const float* w_hh_b   = (const float*)d_in[9];
  const float* b_ih_b   = (const float*)d_in[10];
  const float* b_hh_b   = (const float*)d_in[11];
  const float* w_out    = (const float*)d_in[12];
  const float* b_out    = (const float*)d_in[13];
  float* out = (float*)d_out;

  // one fused init: zero state, pairs, barrier reset, embed, weight converts
  init_kernel<<<(NWO/4 + 255)/256, 256>>>(captions, lengths, emb,
      w_ih_f, w_ih_b, w_hh_f, w_hh_b, w_out);

  // input projections (single-pass fp16, both dirs)
  gemm16_bias<<<dim3(G4/128, (BSZ*NSEQ)/128, 2), 256>>>(b_ih_f, b_hh_f, b_ih_b, b_hh_b);

  // all 20 LSTM steps in one persistent kernel (176 blocks, 2/SM)
  lstm_persist<<<LSTM_BLOCKS, 256>>>();

  // final projection + bias + fused per-group L2 normalize (cp.async, BM=128)
  out_gemm_fused<<<dim3(NOUT/256, (MROWS + 127)/128), 512>>>(b_out, out);
}

// round 17
// speedup vs baseline: 1.1715x; 1.0092x over previous
#include <cuda_runtime.h>
#include <cuda_fp16.h>
#include <stdint.h>

#define BSZ 32
#define NSEQ 20
#define DIM 512
#define HID 512
#define G4 2048          // 4*HID
#define NOUT 7680        // NT*SEM
#define SEM 256
#define NPAIR 190
#define MROWS (BSZ*NPAIR)   // 6080
#define SB (NSEQ*BSZ*HID)   // 640*512 per plane
#define FSZ (BSZ*NSEQ*NSEQ*HID)
#define LSTM_BLOCKS 176     // 16 col-tiles x 11 row-tiles
#define NW (G4*HID)         // 1048576
#define NWO (NOUT*2*HID)    // 7864320

// ---------------- device scratch ----------------
__device__ __half g_WV16[BSZ*NSEQ*DIM];        // masked word vectors fp16
__device__ float g_X[2][BSZ*NSEQ*G4];          // input projections (f, b)
__device__ __half g_H16[2][2][SB];             // [dir][parity] hidden (fp16)
__device__ float g_C[2][SB];                   // cell state
__device__ __half g_WI16[2][G4*DIM];           // W_ih fp16 (f, b)
__device__ __half g_W16[2][G4*HID];            // W_hh fp16 (f, b)
__device__ float g_Ff[FSZ];                    // fp32 cumulative sums
__device__ float g_Fb[FSZ];
__device__ __half g_FF16[FSZ];                 // fp16 cumsum planes (out GEMM)
__device__ __half g_FB16[FSZ];
__device__ __half g_WO16[NOUT*2*HID];          // fp16 w_out
__device__ int   g_psF[NPAIR];
__device__ int   g_psB[NPAIR];
__device__ int   g_pcnt[NPAIR];
__device__ unsigned g_bar;

__device__ __forceinline__ float sigm(float x){ return 1.f/(1.f+__expf(-x)); }

__device__ __forceinline__ void mma16h(float c[4], const uint32_t a[4], const uint32_t b[2]){
  asm volatile("mma.sync.aligned.m16n8k16.row.col.f32.f16.f16.f32 "
      "{%0,%1,%2,%3}, {%4,%5,%6,%7}, {%8,%9}, {%0,%1,%2,%3};\n"
      : "+f"(c[0]), "+f"(c[1]), "+f"(c[2]), "+f"(c[3])
      : "r"(a[0]), "r"(a[1]), "r"(a[2]), "r"(a[3]), "r"(b[0]), "r"(b[1]));
}
__device__ __forceinline__ void ldsm4(uint32_t r[4], uint32_t saddr){
  asm volatile("ldmatrix.sync.aligned.m8n8.x4.shared.b16 {%0,%1,%2,%3}, [%4];"
      : "=r"(r[0]), "=r"(r[1]), "=r"(r[2]), "=r"(r[3]) : "r"(saddr));
}
__device__ __forceinline__ void cpa16(uint32_t dst, const void* src){
  asm volatile("cp.async.cg.shared.global [%0], [%1], 16;" :: "r"(dst), "l"(src) : "memory");
}
#define CPA_COMMIT() asm volatile("cp.async.commit_group;" ::: "memory")
#define CPA_WAIT1()  asm volatile("cp.async.wait_group 1;" ::: "memory")
#define CPA_WAIT0()  asm volatile("cp.async.wait_group 0;" ::: "memory")

__device__ __forceinline__ void st4h(__half* dst, float4 v){
  __half2 h0 = __floats2half2_rn(v.x, v.y);
  __half2 h1 = __floats2half2_rn(v.z, v.w);
  uint2 u;
  u.x = *(uint32_t*)&h0;
  u.y = *(uint32_t*)&h1;
  *(uint2*)dst = u;
}

// =======================================================================
// ONE init kernel: zero state, pairs+barrier, embed, all weight converts.
// =======================================================================
__global__ void init_kernel(const int* __restrict__ cap, const int* __restrict__ len,
                            const float* __restrict__ emb,
                            const float* __restrict__ wih_f, const float* __restrict__ wih_b,
                            const float* __restrict__ whh_f, const float* __restrict__ whh_b,
                            const float* __restrict__ wout)
{
  int e = (blockIdx.x*blockDim.x + threadIdx.x)*4;
  if (e < NWO)
    st4h(&g_WO16[e], *(const float4*)(wout + e));
  if (e < NW){
    st4h(&g_WI16[0][e], *(const float4*)(wih_f + e));
    st4h(&g_WI16[1][e], *(const float4*)(wih_b + e));
    st4h(&g_W16[0][e],  *(const float4*)(whh_f + e));
    st4h(&g_W16[1][e],  *(const float4*)(whh_b + e));
  }
  if (e < 4*SB)
    *(uint2*)(&g_H16[0][0][0] + e) = make_uint2(0u, 0u);
  if (e < 2*SB)
    *(float4*)(&g_C[0][0] + e) = make_float4(0.f, 0.f, 0.f, 0.f);
  if (e < BSZ*NSEQ*DIM){
    int bt = e / DIM, col = e % DIM;
    int b = bt / NSEQ, t = bt % NSEQ;
    float m = (t < len[b]) ? 1.f : 0.f;
    float4 v = *(const float4*)(emb + (size_t)cap[bt]*DIM + col);
    v.x *= m; v.y *= m; v.z *= m; v.w *= m;
    st4h(&g_WV16[e], v);
  }
  if (blockIdx.x == 0){
    if (threadIdx.x == 0) g_bar = 0;
    int p = threadIdx.x;
    if (p < NPAIR){
      int cum = 0, k = 1, s = 0;
      for (int kk = 1; kk < NSEQ; kk++){
        int c = NSEQ - kk;
        if (p < cum + c){ k = kk; s = p - cum; break; }
        cum += c;
      }
      int ee = s + k;
      g_psF[p] = s*NSEQ + ee;
      g_psB[p] = ee*NSEQ + s;
      g_pcnt[p] = k + 1;
    }
  }
}

// =======================================================================
// FP16 projection GEMM: X[dir] = WV16 @ WI16[dir]^T + (b_ih + b_hh)
// =======================================================================
__global__ __launch_bounds__(256) void gemm16_bias(
    const float* __restrict__ bif, const float* __restrict__ bhf,
    const float* __restrict__ bib, const float* __restrict__ bhb)
{
  const int dir = blockIdx.z;
  const __half* __restrict__ A = g_WV16;
  const __half* __restrict__ B = g_WI16[dir];
  const float* __restrict__ b1 = dir ? bib : bif;
  const float* __restrict__ b2 = dir ? bhb : bhf;
  float* __restrict__ C = g_X[dir];

  __shared__ __align__(16) __half sA[128][40];
  __shared__ __align__(16) __half sB[128][40];
  const int tid = threadIdx.x, lane = tid & 31, wid = tid >> 5;
  const int warpM = wid >> 2, warpN = wid & 3;
  const int g = lane >> 2, t4 = lane & 3;
  const int bm = blockIdx.y*128, bn = blockIdx.x*128;

  const uint32_t sAu = (uint32_t)__cvta_generic_to_shared(&sA[0][0]);
  const uint32_t sBu = (uint32_t)__cvta_generic_to_shared(&sB[0][0]);
  const int bmat = lane >> 3;
  const uint32_t aOff = ((uint32_t)(warpM*64 + (lane & 15))*40 + (uint32_t)(lane >> 4)*8)*2;
  const uint32_t bOff = ((uint32_t)(warpN*32 + ((bmat >> 1)*8) + (lane & 7))*40
                        + (uint32_t)(bmat & 1)*8)*2;

  const int arow = tid >> 1, ak = (tid & 1)*16;
  uint4 ra[2], rb[2];
  {
    const __half* srcA = A + (size_t)(bm + arow)*DIM + ak;
    ra[0] = *(const uint4*)srcA;
    ra[1] = *(const uint4*)(srcA + 8);
    const __half* srcB = B + (size_t)(bn + arow)*DIM + ak;
    rb[0] = *(const uint4*)srcB;
    rb[1] = *(const uint4*)(srcB + 8);
  }

  float acc[4][4][4] = {};
  for (int k0 = 0; k0 < DIM; k0 += 32){
    __syncthreads();
    *(uint4*)&sA[arow][ak]     = ra[0];
    *(uint4*)&sA[arow][ak + 8] = ra[1];
    *(uint4*)&sB[arow][ak]     = rb[0];
    *(uint4*)&sB[arow][ak + 8] = rb[1];
    __syncthreads();
    if (k0 + 32 < DIM){
      const __half* srcA = A + (size_t)(bm + arow)*DIM + k0 + 32 + ak;
      ra[0] = *(const uint4*)srcA;
      ra[1] = *(const uint4*)(srcA + 8);
      const __half* srcB = B + (size_t)(bn + arow)*DIM + k0 + 32 + ak;
      rb[0] = *(const uint4*)srcB;
      rb[1] = *(const uint4*)(srcB + 8);
    }
    #pragma unroll
    for (int ks = 0; ks < 32; ks += 16){
      uint32_t a[4][4], bq[2][4];
      #pragma unroll
      for (int mt = 0; mt < 4; mt++)
        ldsm4(a[mt], sAu + aOff + (uint32_t)mt*16*80 + (uint32_t)ks*2);
      ldsm4(bq[0], sBu + bOff + (uint32_t)ks*2);
      ldsm4(bq[1], sBu + bOff + 16*80 + (uint32_t)ks*2);
      #pragma unroll
      for (int mt = 0; mt < 4; mt++)
        #pragma unroll
        for (int nt = 0; nt < 4; nt++)
          mma16h(acc[mt][nt], a[mt], &bq[nt>>1][(nt&1)*2]);
    }
  }
  #pragma unroll
  for (int mt = 0; mt < 4; mt++){
    int gm0 = bm + warpM*64 + mt*16 + g;
    #pragma unroll
    for (int nt = 0; nt < 4; nt++){
      int gn = bn + warpN*32 + nt*8 + 2*t4;
      float e0 = b1[gn] + b2[gn], e1 = b1[gn+1] + b2[gn+1];
      C[(size_t)gm0*G4 + gn]         = acc[mt][nt][0] + e0;
      C[(size_t)gm0*G4 + gn + 1]     = acc[mt][nt][1] + e1;
      C[(size_t)(gm0+8)*G4 + gn]     = acc[mt][nt][2] + e0;
      C[(size_t)(gm0+8)*G4 + gn + 1] = acc[mt][nt][3] + e1;
    }
  }
}

// =======================================================================
// Persistent LSTM: 176 blocks, 2 blocks/SM, pipelined fragment loads.
// =======================================================================
__device__ __forceinline__ void grid_sync(unsigned target){
  __syncthreads();
  if (threadIdx.x == 0){
    __threadfence();
    atomicAdd(&g_bar, 1u);
    while (atomicAdd(&g_bar, 0u) < target) {}
    __threadfence();
  }
  __syncthreads();
}

__global__ __launch_bounds__(256, 2) void lstm_persist()
{
  const int n0 = (blockIdx.x & 15) * 32;     // 32-col tile
  const int rt = blockIdx.x >> 4;            // 0..10
  const int tid = threadIdx.x, lane = tid & 31, wid = tid >> 5;
  const int warpM = wid & 3, warpN = wid >> 2;   // 4M x 2N
  const int g8 = lane >> 2, t4 = lane & 3;

  __shared__ __align__(16) uint16_t sA[64][24];    // 3072 B
  __shared__ __align__(16) uint16_t sB[128][24];   // 6144 B
  const uint32_t sAu = (uint32_t)__cvta_generic_to_shared(&sA[0][0]);
  const uint32_t sBu = (uint32_t)__cvta_generic_to_shared(&sB[0][0]);
  const int bmat = lane >> 3;
  const uint32_t aOff = ((uint32_t)(warpM*16 + (lane & 15))*24 + (uint32_t)(lane >> 4)*8)*2;
  const uint32_t bOff = ((uint32_t)(warpN*16 + ((bmat >> 1)*8) + (lane & 7))*24
                        + (uint32_t)(bmat & 1)*8)*2;
  const int arow = tid >> 1, ak8 = (tid & 1)*8;
  const int rbr = tid >> 1;                  // 0..127 B rows
  const int bk8 = (tid & 1)*8;

  for (int j = 0; j < NSEQ; j++){
    const int p = j & 1;
    const int tf = (j + 2) >> 1;             // ceil((j+1)/2) forward row tiles
    int dir, bm, rowLim;
    if (rt < tf){ dir = 0; bm = rt*64;                   rowLim = (j+1)*BSZ; }
    else        { dir = 1; bm = j*BSZ + (rt - tf)*64;    rowLim = NSEQ*BSZ; }

    const __half* __restrict__ Ain = g_H16[dir][p];
    const __half* __restrict__ W = g_W16[dir];
    const int gr = bm + arow;
    const bool aok = (gr < rowLim);
    const int wrow = (rbr >> 5)*HID + n0 + (rbr & 31);   // gate*512 + col

    float acc[4][2][4] = {};
    uint4 ra, rb;
    if (tid < 128)
      ra = aok ? *(const uint4*)(Ain + (size_t)gr*HID + ak8) : make_uint4(0,0,0,0);
    rb = *(const uint4*)(W + (size_t)wrow*HID + bk8);

    for (int k0 = 0; k0 < HID; k0 += 16){
      __syncthreads();
      if (tid < 128) *(uint4*)&sA[arow][ak8] = ra;
      *(uint4*)&sB[rbr][bk8] = rb;
      __syncthreads();
      if (k0 + 16 < HID){
        int kn = k0 + 16;
        if (tid < 128)
          ra = aok ? *(const uint4*)(Ain + (size_t)gr*HID + kn + ak8) : make_uint4(0,0,0,0);
        rb = *(const uint4*)(W + (size_t)wrow*HID + kn + bk8);
      }
      // pipelined fragments: prefetch bq for g+1 before mma of g
      uint32_t af[4], bqA[2][4];
      ldsm4(af, sAu + aOff);
      ldsm4(bqA[0], sBu + bOff);
      #pragma unroll
      for (int g = 0; g < 4; g++){
        const int cur = g & 1;
        if (g < 3)
          ldsm4(bqA[cur^1], sBu + (uint32_t)(g+1)*32*48 + bOff);
        mma16h(acc[g][0], af, &bqA[cur][0]);
        mma16h(acc[g][1], af, &bqA[cur][2]);
      }
    }

    // ---- epilogue: gates -> c,h -> state + cumulative F (32 cols/block) ----
    {
      const float* __restrict__ X = g_X[dir];
      float* __restrict__ C = g_C[dir];
      __half* __restrict__ Hn = g_H16[dir][p^1];
      float* __restrict__ F  = dir ? g_Fb  : g_Ff;
      __half* __restrict__ F16 = dir ? g_FB16 : g_FF16;

      #pragma unroll
      for (int rr = 0; rr < 2; rr++){
        int gm = bm + warpM*16 + g8 + rr*8;
        if (gm >= rowLim) continue;
        int chain = gm >> 5, b = gm & 31;
        int t = dir ? (chain - j) : j;
        size_t xrow = (size_t)(b*NSEQ + t)*G4;
        size_t fbase;
        bool first;
        if (dir == 0){ fbase = ((size_t)(b*NSEQ + chain)*NSEQ + j)*HID; first = (j == chain); }
        else         { fbase = ((size_t)(b*NSEQ + chain)*NSEQ + t)*HID; first = (t == chain); }
        #pragma unroll
        for (int nt = 0; nt < 2; nt++){
          #pragma unroll
          for (int cc = 0; cc < 2; cc++){
            int n = n0 + warpN*16 + nt*8 + t4*2 + cc;
            int ai = rr*2 + cc;
            float gi = acc[0][nt][ai] + X[xrow + n];
            float gf = acc[1][nt][ai] + X[xrow + 512 + n];
            float gc = acc[2][nt][ai] + X[xrow + 1024 + n];
            float go = acc[3][nt][ai] + X[xrow + 1536 + n];
            size_t si = (size_t)gm*HID + n;
            float c = sigm(gf)*C[si] + sigm(gi)*tanhf(gc);
            float h = sigm(go)*tanhf(c);
            C[si] = c;
            Hn[si] = __float2half(h);
            float prev = first ? 0.f : F[fbase + n + (dir ? (int)HID : -(int)HID)];
            float v = prev + h;
            F[fbase + n]   = v;
            F16[fbase + n] = __float2half(v);
          }
        }
      }
    }
    grid_sync((unsigned)(LSTM_BLOCKS*(j+1)));
  }
}

// =======================================================================
// out GEMM + fused L2 normalize: cp.async 3-stage + pipelined fragments.
// BM=128, BN=256, 512 threads = 16 warps (4M x 4N). grid (30, 48).
// =======================================================================
#define OGA 10240u     // A stage stride: 128*40*2
#define OGB 20480u     // B stage stride: 256*40*2

__global__ __launch_bounds__(512) void out_gemm_fused(const float* __restrict__ bout,
                                                      float* __restrict__ out)
{
  __shared__ __align__(16) __half sA[3][128][40];
  __shared__ __align__(16) __half sB[3][256][40];
  __shared__ int offF[128], offB[128], cnt[128];
  __shared__ float ssb[4][128];
  const int tid = threadIdx.x, lane = tid & 31, wid = tid >> 5;
  const int warpM = wid >> 2, warpN = wid & 3;
  const int g = lane >> 2, t4 = lane & 3;
  const int bm = blockIdx.y*128, bn = blockIdx.x*256;

  if (tid < 128){
    int gm = bm + tid;
    if (gm < MROWS){
      int b = gm / NPAIR, p = gm % NPAIR;
      offF[tid] = (b*NSEQ*NSEQ + g_psF[p])*HID;
      offB[tid] = (b*NSEQ*NSEQ + g_psB[p])*HID;
      cnt[tid]  = g_pcnt[p];
    } else { offF[tid] = 0; offB[tid] = 0; cnt[tid] = 0; }
  }
  __syncthreads();

  const uint32_t sAu = (uint32_t)__cvta_generic_to_shared(&sA[0][0][0]);
  const uint32_t sBu = (uint32_t)__cvta_generic_to_shared(&sB[0][0][0]);
  const int bmat = lane >> 3;
  const uint32_t aOff = ((uint32_t)(warpM*32 + (lane & 15))*40 + (uint32_t)(lane >> 4)*8)*2;
  const uint32_t bOff = ((uint32_t)(warpN*64 + ((bmat >> 1)*8) + (lane & 7))*40
                        + (uint32_t)(bmat & 1)*8)*2;

  const int arow = tid >> 2, ak = (tid & 3)*8;
  const int aF = offF[arow], aB = offB[arow];
  const uint32_t aDst = sAu + ((uint32_t)arow*40 + (uint32_t)ak)*2;
  uint32_t bDst[2];
  const __half* bSrc[2];
  #pragma unroll
  for (int s = 0; s < 2; s++){
    int idx = tid + s*512;
    int br = idx >> 2, bk = (idx & 3)*8;
    bDst[s] = sBu + ((uint32_t)br*40 + (uint32_t)bk)*2;
    bSrc[s] = g_WO16 + (size_t)(bn + br)*(2*HID) + bk;
  }

  #define OG_ISSUE(stg, it) do{                                               \
    int k_ = (it)*32 + ak;                                                    \
    const __half* srcA_ = (k_ < HID) ? (g_FF16 + aF + k_)                     \
                                     : (g_FB16 + aB + k_ - HID);              \
    cpa16(aDst + (uint32_t)(stg)*OGA, srcA_);                                 \
    _Pragma("unroll")                                                         \
    for (int s_ = 0; s_ < 2; s_++)                                            \
      cpa16(bDst[s_] + (uint32_t)(stg)*OGB, bSrc[s_] + (it)*32);              \
    CPA_COMMIT();                                                             \
  } while(0)

  OG_ISSUE(0, 0);
  OG_ISSUE(1, 1);

  float acc[2][8][4] = {};
  int stg = 0;
  for (int it = 0; it < 32; it++){
    if (it >= 30) CPA_WAIT0(); else CPA_WAIT1();
    __syncthreads();
    if (it + 2 < 32){
      int ns = stg + 2; if (ns >= 3) ns -= 3;
      OG_ISSUE(ns, it + 2);
    }
    // pipelined compute: 8 flattened steps (ks in {0,16}, q in 0..3)
    const uint32_t sAb = sAu + (uint32_t)stg*OGA + aOff;
    const uint32_t sBb = sBu + (uint32_t)stg*OGB + bOff;
    uint32_t aA[2][2][4];          // [ks-half][mt]
    uint32_t bqA[2][4];            // ping-pong
    ldsm4(aA[0][0], sAb);
    ldsm4(aA[0][1], sAb + 16*80);
    ldsm4(bqA[0], sBb);
    #pragma unroll
    for (int s = 0; s < 8; s++){
      const int cur = s & 1;
      const int ah = (s >> 2) & 1;
      if (s < 7){
        const int sn = s + 1;
        const int ksn = (sn >> 2)*16, qn = sn & 3;
        if (sn == 4){
          ldsm4(aA[1][0], sAb + 32);
          ldsm4(aA[1][1], sAb + 16*80 + 32);
        }
        ldsm4(bqA[cur^1], sBb + (uint32_t)qn*16*80 + (uint32_t)ksn*2);
      }
      const int q = s & 3;
      mma16h(acc[0][q*2],     aA[ah][0], &bqA[cur][0]);
      mma16h(acc[0][q*2 + 1], aA[ah][0], &bqA[cur][2]);
      mma16h(acc[1][q*2],     aA[ah][1], &bqA[cur][0]);
      mma16h(acc[1][q*2 + 1], aA[ah][1], &bqA[cur][2]);
    }
    if (++stg >= 3) stg = 0;
  }

  // ---- epilogue: + cnt*bias, fused L2-normalize over the 256-wide group ----
  const int r0 = warpM*32 + g;
  float ssr[2][2] = {};
  #pragma unroll
  for (int mt = 0; mt < 2; mt++){
    int rl = r0 + mt*16;
    float c0 = (float)cnt[rl], c1 = (float)cnt[rl + 8];
    #pragma unroll
    for (int nt = 0; nt < 8; nt++){
      int gn = bn + warpN*64 + nt*8 + 2*t4;
      float b0 = bout[gn], b1 = bout[gn + 1];
      acc[mt][nt][0] += c0*b0;  acc[mt][nt][1] += c0*b1;
      acc[mt][nt][2] += c1*b0;  acc[mt][nt][3] += c1*b1;
      ssr[mt][0] += acc[mt][nt][0]*acc[mt][nt][0] + acc[mt][nt][1]*acc[mt][nt][1];
      ssr[mt][1] += acc[mt][nt][2]*acc[mt][nt][2] + acc[mt][nt][3]*acc[mt][nt][3];
    }
  }
  #pragma unroll
  for (int mt = 0; mt < 2; mt++)
    #pragma unroll
    for (int pq = 0; pq < 2; pq++){
      ssr[mt][pq] += __shfl_xor_sync(0xffffffffu, ssr[mt][pq], 1);
      ssr[mt][pq] += __shfl_xor_sync(0xffffffffu, ssr[mt][pq], 2);
    }
  __syncthreads();
  if (t4 == 0){
    ssb[warpN][r0]      = ssr[0][0];
    ssb[warpN][r0 + 8]  = ssr[0][1];
    ssb[warpN][r0 + 16] = ssr[1][0];
    ssb[warpN][r0 + 24] = ssr[1][1];
  }
  __syncthreads();
  #pragma unroll
  for (int mt = 0; mt < 2; mt++){
    #pragma unroll
    for (int pq = 0; pq < 2; pq++){
      int rl = r0 + mt*16 + pq*8;
      int gm = bm + rl;
      float tot = ssb[0][rl] + ssb[1][rl] + ssb[2][rl] + ssb[3][rl];
      float sc = 1.f / fmaxf(sqrtf(tot), 1e-12f);
      if (gm < MROWS){
        #pragma unroll
        for (int nt = 0; nt < 8; nt++){
          int gn = bn + warpN*64 + nt*8 + 2*t4;
          float2 v;
          v.x = acc[mt][nt][pq*2]     * sc;
          v.y = acc[mt][nt][pq*2 + 1] * sc;
          *(float2*)(out + (size_t)gm*NOUT + gn) = v;
        }
      }
    }
  }
}

// ---------------- launcher ----------------
extern "C" void kernel_launch(void* const* d_in, const int* in_sizes, int n_in,
                              void* d_out, int out_size)
{
  const int*   captions = (const int*)  d_in[1];
  const int*   lengths  = (const int*)  d_in[2];
  const float* emb      = (const float*)d_in[3];
  const float* w_ih_f   = (const float*)d_in[4];
  const float* w_hh_f   = (const float*)d_in[5];
  const float* b_ih_f   = (const float*)d_in[6];
  const float* b_hh_f   = (const float*)d_in[7];
  const float* w_ih_b   = (const float*)d_in[8];
  const float* w_hh_b   = (const float*)d_in[9];
  const float* b_ih_b   = (const float*)d_in[10];
  const float* b_hh_b   = (const float*)d_in[11];
  const float* w_out    = (const float*)d_in[12];
  const float* b_out    = (const float*)d_in[13];
  float* out = (float*)d_out;

  init_kernel<<<(NWO/4 + 255)/256, 256>>>(captions, lengths, emb,
      w_ih_f, w_ih_b, w_hh_f, w_hh_b, w_out);

  gemm16_bias<<<dim3(G4/128, (BSZ*NSEQ)/128, 2), 256>>>(b_ih_f, b_hh_f, b_ih_b, b_hh_b);

  lstm_persist<<<LSTM_BLOCKS, 256>>>();

  out_gemm_fused<<<dim3(NOUT/256, (MROWS + 127)/128), 512>>>(b_out, out);
}